// round 1
// baseline (speedup 1.0000x reference)
#include <cuda_runtime.h>
#include <math.h>

// Problem dims
#define BQ 16
#define CQ 512
#define NQ 4096   // H*W
#define KQ 64

// Scratch (allocation-free rule: device globals)
__device__ __align__(128) float g_y   [BQ * CQ * NQ];  // conv1 output
__device__ __align__(128) float g_attn[BQ * KQ * NQ];  // attention logits / probs
__device__ __align__(128) float g_y2  [BQ * CQ * NQ];  // lin1 output / ranked

// ---------------------------------------------------------------------------
// Generic batched SGEMM: Out[b][m][n] = sum_k A[m][k] * Bm[b][k][n]  (+epilogue)
// A shared across batch (row-major M x Kc). Bm row-major Kc x Nn per batch.
// EPI: 0 = plain store, 1 = +bias[m], 2 = relu -> +resid[b][m][n] -> relu
// ---------------------------------------------------------------------------
template<int M, int Kc, int Nn, int BM, int BN, int BK, int TM, int TN, int EPI>
__global__ __launch_bounds__((BM/TM)*(BN/TN))
void sgemm_kernel(const float* __restrict__ A,
                  const float* __restrict__ Bm,
                  const float* __restrict__ bias,
                  const float* __restrict__ resid,
                  float* __restrict__ Out)
{
    constexpr int THREADS = (BM/TM)*(BN/TN);
    __shared__ float As[BK][BM];
    __shared__ float Bs[BK][BN];

    const int b   = blockIdx.z;
    const int bm0 = blockIdx.y * BM;
    const int bn0 = blockIdx.x * BN;
    const float* Bp = Bm + (size_t)b * Kc * Nn;
    float*       Op = Out + (size_t)b * M * Nn;

    const int tid = threadIdx.x;
    const int tx  = tid % (BN/TN);
    const int ty  = tid / (BN/TN);

    float acc[TM][TN];
    #pragma unroll
    for (int i = 0; i < TM; i++)
        #pragma unroll
        for (int j = 0; j < TN; j++) acc[i][j] = 0.f;

    for (int k0 = 0; k0 < Kc; k0 += BK) {
        // A tile: BM x BK (row-major, lda = Kc), store transposed to As[k][m]
        #pragma unroll
        for (int idx = tid * 4; idx < BM * BK; idx += THREADS * 4) {
            int r = idx / BK;
            int c = idx % BK;
            float4 v = *reinterpret_cast<const float4*>(&A[(size_t)(bm0 + r) * Kc + k0 + c]);
            As[c + 0][r] = v.x; As[c + 1][r] = v.y;
            As[c + 2][r] = v.z; As[c + 3][r] = v.w;
        }
        // B tile: BK x BN (rows contiguous in n)
        #pragma unroll
        for (int idx = tid * 4; idx < BK * BN; idx += THREADS * 4) {
            int r = idx / BN;
            int c = idx % BN;
            *reinterpret_cast<float4*>(&Bs[r][c]) =
                *reinterpret_cast<const float4*>(&Bp[(size_t)(k0 + r) * Nn + bn0 + c]);
        }
        __syncthreads();

        #pragma unroll
        for (int k = 0; k < BK; k++) {
            float a[TM], bb[TN];
            #pragma unroll
            for (int i = 0; i < TM; i++) a[i] = As[k][ty * TM + i];
            #pragma unroll
            for (int j = 0; j < TN; j++) bb[j] = Bs[k][tx * TN + j];
            #pragma unroll
            for (int i = 0; i < TM; i++)
                #pragma unroll
                for (int j = 0; j < TN; j++)
                    acc[i][j] += a[i] * bb[j];
        }
        __syncthreads();
    }

    // Epilogue, vectorized stores (TN % 4 == 0)
    #pragma unroll
    for (int i = 0; i < TM; i++) {
        const int m = bm0 + ty * TM + i;
        float bval = 0.f;
        if (EPI == 1) bval = bias[m];
        #pragma unroll
        for (int j = 0; j < TN; j += 4) {
            const int n = bn0 + tx * TN + j;
            float4 o;
            float vv[4];
            #pragma unroll
            for (int u = 0; u < 4; u++) vv[u] = acc[i][j + u];
            if (EPI == 1) {
                #pragma unroll
                for (int u = 0; u < 4; u++) vv[u] += bval;
            }
            if (EPI == 2) {
                float4 r = *reinterpret_cast<const float4*>(
                    &resid[(size_t)b * M * Nn + (size_t)m * Nn + n]);
                vv[0] = fmaxf(fmaxf(vv[0], 0.f) + r.x, 0.f);
                vv[1] = fmaxf(fmaxf(vv[1], 0.f) + r.y, 0.f);
                vv[2] = fmaxf(fmaxf(vv[2], 0.f) + r.z, 0.f);
                vv[3] = fmaxf(fmaxf(vv[3], 0.f) + r.w, 0.f);
            }
            o.x = vv[0]; o.y = vv[1]; o.z = vv[2]; o.w = vv[3];
            *reinterpret_cast<float4*>(&Op[(size_t)m * Nn + n]) = o;
        }
    }
}

// ---------------------------------------------------------------------------
// Softmax over the token axis (length NQ) for each (b, k) row. 256 threads.
// ---------------------------------------------------------------------------
__global__ __launch_bounds__(256) void softmax_kernel(float* __restrict__ attn)
{
    const int row = blockIdx.x;                 // 0 .. B*K-1
    float* p = attn + (size_t)row * NQ;
    const int tid = threadIdx.x;
    __shared__ float red[256];

    float v[NQ / 256];
    float m = -INFINITY;
    #pragma unroll
    for (int i = 0; i < NQ / 256; i++) {
        v[i] = p[tid + i * 256];
        m = fmaxf(m, v[i]);
    }
    red[tid] = m; __syncthreads();
    for (int s = 128; s > 0; s >>= 1) {
        if (tid < s) red[tid] = fmaxf(red[tid], red[tid + s]);
        __syncthreads();
    }
    m = red[0]; __syncthreads();

    float s = 0.f;
    #pragma unroll
    for (int i = 0; i < NQ / 256; i++) {
        v[i] = expf(v[i] - m);
        s += v[i];
    }
    red[tid] = s; __syncthreads();
    for (int st = 128; st > 0; st >>= 1) {
        if (tid < st) red[tid] += red[tid + st];
        __syncthreads();
    }
    const float inv = 1.f / red[0];
    #pragma unroll
    for (int i = 0; i < NQ / 256; i++) p[tid + i * 256] = v[i] * inv;
}

// ---------------------------------------------------------------------------
// L1 renorm over latent axis K for each (b, n): attn /= (1e-9 + sum_k attn)
// Coalesced: consecutive threads handle consecutive n.
// ---------------------------------------------------------------------------
__global__ __launch_bounds__(256) void renorm_kernel(float* __restrict__ attn)
{
    const int idx = blockIdx.x * blockDim.x + threadIdx.x;  // over B*NQ
    if (idx >= BQ * NQ) return;
    const int b = idx / NQ, n = idx % NQ;
    float* p = attn + (size_t)b * KQ * NQ + n;
    float s = 0.f;
    #pragma unroll
    for (int k = 0; k < KQ; k++) s += p[(size_t)k * NQ];
    const float inv = 1.f / (1e-9f + s);
    #pragma unroll
    for (int k = 0; k < KQ; k++) p[(size_t)k * NQ] *= inv;
}

// ---------------------------------------------------------------------------
// Rank step: view(-1, C) on the (b, c, n) tensor makes each "row" a 512-element
// CONTIGUOUS chunk (since NQ = 8 * CQ... actually each row is 512 consecutive
// floats of the flat array). thr = 256th largest per row (= ascending[256] of
// 512). out = (v < thr) ? 0.75v : 1.25v. Bitonic sort in shared memory.
// ---------------------------------------------------------------------------
__global__ __launch_bounds__(256) void rank_kernel(float* __restrict__ y2)
{
    const int row = blockIdx.x;                 // 0 .. (B*C*NQ/512)-1
    float* p = y2 + (size_t)row * 512;
    const int tid = threadIdx.x;
    __shared__ float s[512];

    const float v0 = p[tid];
    const float v1 = p[tid + 256];
    s[tid] = v0; s[tid + 256] = v1;
    __syncthreads();

    // bitonic ascending sort of 512 elements with 256 threads
    for (int k = 2; k <= 512; k <<= 1) {
        for (int j = k >> 1; j > 0; j >>= 1) {
            int i = ((tid & ~(j - 1)) << 1) | (tid & (j - 1));
            int partner = i | j;
            bool up = ((i & k) == 0);
            float a = s[i], bb = s[partner];
            if ((a > bb) == up) { s[i] = bb; s[partner] = a; }
            __syncthreads();
        }
    }
    const float thr = s[256];  // 256th largest of 512
    p[tid]       = (v0 < thr) ? 0.75f * v0 : 1.25f * v0;
    p[tid + 256] = (v1 < thr) ? 0.75f * v1 : 1.25f * v1;
}

// ---------------------------------------------------------------------------
// Launch
// ---------------------------------------------------------------------------
extern "C" void kernel_launch(void* const* d_in, const int* in_sizes, int n_in,
                              void* d_out, int out_size)
{
    const float* x  = (const float*)d_in[0];  // (B, C, H, W)
    const float* w1 = (const float*)d_in[1];  // (C, C)
    const float* b1 = (const float*)d_in[2];  // (C,)
    const float* l0 = (const float*)d_in[3];  // (K, C)
    const float* l1 = (const float*)d_in[4];  // (C, K)
    const float* w2 = (const float*)d_in[5];  // (C, C)
    float* out = (float*)d_out;

    void *yp_, *ap_, *y2p_;
    cudaGetSymbolAddress(&yp_, g_y);
    cudaGetSymbolAddress(&ap_, g_attn);
    cudaGetSymbolAddress(&y2p_, g_y2);
    float* y    = (float*)yp_;
    float* attn = (float*)ap_;
    float* y2   = (float*)y2p_;

    // conv1: y = W1 @ x + b1
    sgemm_kernel<CQ, CQ, NQ, 128, 128, 8, 8, 8, 1>
        <<<dim3(NQ / 128, CQ / 128, BQ), 256>>>(w1, x, b1, nullptr, y);

    // lin0: attn = L0 @ y
    sgemm_kernel<KQ, CQ, NQ, 64, 128, 16, 4, 8, 0>
        <<<dim3(NQ / 128, 1, BQ), 256>>>(l0, y, nullptr, nullptr, attn);

    // softmax over tokens
    softmax_kernel<<<BQ * KQ, 256>>>(attn);

    // L1 renorm over latent dim
    renorm_kernel<<<(BQ * NQ) / 256, 256>>>(attn);

    // lin1: y2 = L1 @ attn
    sgemm_kernel<CQ, KQ, NQ, 128, 128, 8, 8, 8, 0>
        <<<dim3(NQ / 128, CQ / 128, BQ), 256>>>(l1, attn, nullptr, nullptr, y2);

    // rank (threshold scaling over 512-contiguous chunks)
    rank_kernel<<<(BQ * CQ * NQ) / 512, 256>>>(y2);

    // conv2 + relu + residual + relu
    sgemm_kernel<CQ, CQ, NQ, 128, 128, 8, 8, 8, 2>
        <<<dim3(NQ / 128, CQ / 128, BQ), 256>>>(w2, y2, nullptr, x, out);
}

// round 2
// speedup vs baseline: 1.3022x; 1.3022x over previous
#include <cuda_runtime.h>
#include <math.h>

// Problem dims
#define BQ 16
#define CQ 512
#define NQ 4096   // H*W
#define KQ 64

// Scratch (allocation-free rule: device globals)
__device__ __align__(128) float g_y   [BQ * CQ * NQ];  // conv1 output
__device__ __align__(128) float g_attn[BQ * KQ * NQ];  // attention logits / probs
__device__ __align__(128) float g_y2  [BQ * CQ * NQ];  // lin1 output / ranked
__device__ __align__(128) float g_w1T [CQ * CQ];       // conv1 weight, transposed [c][o]
__device__ __align__(128) float g_w2T [CQ * CQ];       // conv2 weight, transposed [c][o]
__device__ __align__(128) float g_l0T [CQ * KQ];       // lin0 weight, transposed [c][k]
__device__ __align__(128) float g_l1T [KQ * CQ];       // lin1 weight, transposed [k][c]

// ---------------------------------------------------------------------------
// cp.async helpers (16B, global -> shared)
// ---------------------------------------------------------------------------
__device__ __forceinline__ void cpa16(void* smem_dst, const void* gmem_src) {
    unsigned sa = (unsigned)__cvta_generic_to_shared(smem_dst);
    asm volatile("cp.async.ca.shared.global [%0], [%1], 16;" :: "r"(sa), "l"(gmem_src));
}
__device__ __forceinline__ void cpa_commit() {
    asm volatile("cp.async.commit_group;" ::: "memory");
}
__device__ __forceinline__ void cpa_wait0() {
    asm volatile("cp.async.wait_group 0;" ::: "memory");
}

// ---------------------------------------------------------------------------
// Transpose: AT[k][m] = A[m][k].  M, K multiples of 32.
// ---------------------------------------------------------------------------
__global__ __launch_bounds__(256) void transpose_kernel(
    const float* __restrict__ A, float* __restrict__ AT, int M, int K)
{
    __shared__ float t[32][33];
    const int m0 = blockIdx.y * 32, k0 = blockIdx.x * 32;
    const int x = threadIdx.x, y = threadIdx.y;   // block (32, 8)
    #pragma unroll
    for (int yy = y; yy < 32; yy += 8)
        t[yy][x] = A[(size_t)(m0 + yy) * K + k0 + x];
    __syncthreads();
    #pragma unroll
    for (int yy = y; yy < 32; yy += 8)
        AT[(size_t)(k0 + yy) * M + m0 + x] = t[x][yy];
}

// ---------------------------------------------------------------------------
// SGEMM-NT: Out[b][m][n] = sum_k AT[k][m] * Bm[b][k][n]  (+epilogue)
// AT row-major Kc x M (transposed weight, shared across batch).
// Bm row-major Kc x Nn per batch. Double-buffered cp.async pipeline.
// EPI: 0 = plain store, 1 = +bias[m], 2 = relu -> +resid[b][m][n] -> relu
// Accumulation order: k strictly ascending (bit-compatible with R1 math).
// ---------------------------------------------------------------------------
template<int M, int Kc, int Nn, int BM, int BN, int BK, int TM, int TN, int EPI>
__global__ __launch_bounds__((BM/TM)*(BN/TN))
void gemm_nt_kernel(const float* __restrict__ AT,
                    const float* __restrict__ Bm,
                    const float* __restrict__ bias,
                    const float* __restrict__ resid,
                    float* __restrict__ Out)
{
    constexpr int THREADS = (BM/TM)*(BN/TN);
    __shared__ float As[2][BK][BM];
    __shared__ float Bs[2][BK][BN];

    const int b   = blockIdx.z;
    const int bm0 = blockIdx.y * BM;
    const int bn0 = blockIdx.x * BN;
    const float* Bp = Bm + (size_t)b * Kc * Nn;
    float*       Op = Out + (size_t)b * M * Nn;

    const int tid = threadIdx.x;
    const int tx  = tid % (BN/TN);
    const int ty  = tid / (BN/TN);

    float acc[TM][TN];
    #pragma unroll
    for (int i = 0; i < TM; i++)
        #pragma unroll
        for (int j = 0; j < TN; j++) acc[i][j] = 0.f;

    auto load_tile = [&](int k0, int s) {
        #pragma unroll
        for (int i = tid; i < BK*BM/4; i += THREADS) {
            int k = (i*4) / BM, m = (i*4) % BM;
            cpa16(&As[s][k][m], &AT[(size_t)(k0 + k) * M + bm0 + m]);
        }
        #pragma unroll
        for (int i = tid; i < BK*BN/4; i += THREADS) {
            int k = (i*4) / BN, n = (i*4) % BN;
            cpa16(&Bs[s][k][n], &Bp[(size_t)(k0 + k) * Nn + bn0 + n]);
        }
        cpa_commit();
    };

    constexpr int NT = Kc / BK;
    load_tile(0, 0);

    for (int t = 0; t < NT; t++) {
        cpa_wait0();
        __syncthreads();
        if (t + 1 < NT) load_tile((t + 1) * BK, (t + 1) & 1);

        const int s = t & 1;
        float a[2][TM], bb[2][TN];
        #pragma unroll
        for (int v = 0; v < TM; v += 4)
            *reinterpret_cast<float4*>(&a[0][v]) =
                *reinterpret_cast<const float4*>(&As[s][0][ty*TM + v]);
        #pragma unroll
        for (int v = 0; v < TN; v += 4)
            *reinterpret_cast<float4*>(&bb[0][v]) =
                *reinterpret_cast<const float4*>(&Bs[s][0][tx*TN + v]);

        #pragma unroll
        for (int k = 0; k < BK; k++) {
            if (k + 1 < BK) {
                #pragma unroll
                for (int v = 0; v < TM; v += 4)
                    *reinterpret_cast<float4*>(&a[(k+1)&1][v]) =
                        *reinterpret_cast<const float4*>(&As[s][k+1][ty*TM + v]);
                #pragma unroll
                for (int v = 0; v < TN; v += 4)
                    *reinterpret_cast<float4*>(&bb[(k+1)&1][v]) =
                        *reinterpret_cast<const float4*>(&Bs[s][k+1][tx*TN + v]);
            }
            const int c = k & 1;
            #pragma unroll
            for (int i = 0; i < TM; i++)
                #pragma unroll
                for (int j = 0; j < TN; j++)
                    acc[i][j] += a[c][i] * bb[c][j];
        }
    }

    #pragma unroll
    for (int i = 0; i < TM; i++) {
        const int m = bm0 + ty * TM + i;
        float bval = 0.f;
        if (EPI == 1) bval = bias[m];
        #pragma unroll
        for (int j = 0; j < TN; j += 4) {
            const int n = bn0 + tx * TN + j;
            float vv[4];
            #pragma unroll
            for (int u = 0; u < 4; u++) vv[u] = acc[i][j + u];
            if (EPI == 1) {
                #pragma unroll
                for (int u = 0; u < 4; u++) vv[u] += bval;
            }
            if (EPI == 2) {
                float4 r = *reinterpret_cast<const float4*>(
                    &resid[(size_t)b * M * Nn + (size_t)m * Nn + n]);
                vv[0] = fmaxf(fmaxf(vv[0], 0.f) + r.x, 0.f);
                vv[1] = fmaxf(fmaxf(vv[1], 0.f) + r.y, 0.f);
                vv[2] = fmaxf(fmaxf(vv[2], 0.f) + r.z, 0.f);
                vv[3] = fmaxf(fmaxf(vv[3], 0.f) + r.w, 0.f);
            }
            float4 o; o.x = vv[0]; o.y = vv[1]; o.z = vv[2]; o.w = vv[3];
            *reinterpret_cast<float4*>(&Op[(size_t)m * Nn + n]) = o;
        }
    }
}

// ---------------------------------------------------------------------------
// Softmax over the token axis (length NQ) for each (b, k) row. 256 threads.
// ---------------------------------------------------------------------------
__global__ __launch_bounds__(256) void softmax_kernel(float* __restrict__ attn)
{
    const int row = blockIdx.x;                 // 0 .. B*K-1
    float* p = attn + (size_t)row * NQ;
    const int tid = threadIdx.x;
    __shared__ float red[256];

    float v[NQ / 256];
    float m = -INFINITY;
    #pragma unroll
    for (int i = 0; i < NQ / 256; i++) {
        v[i] = p[tid + i * 256];
        m = fmaxf(m, v[i]);
    }
    red[tid] = m; __syncthreads();
    for (int s = 128; s > 0; s >>= 1) {
        if (tid < s) red[tid] = fmaxf(red[tid], red[tid + s]);
        __syncthreads();
    }
    m = red[0]; __syncthreads();

    float s = 0.f;
    #pragma unroll
    for (int i = 0; i < NQ / 256; i++) {
        v[i] = expf(v[i] - m);
        s += v[i];
    }
    red[tid] = s; __syncthreads();
    for (int st = 128; st > 0; st >>= 1) {
        if (tid < st) red[tid] += red[tid + st];
        __syncthreads();
    }
    const float inv = 1.f / red[0];
    #pragma unroll
    for (int i = 0; i < NQ / 256; i++) p[tid + i * 256] = v[i] * inv;
}

// ---------------------------------------------------------------------------
// L1 renorm over latent axis K for each (b, n)
// ---------------------------------------------------------------------------
__global__ __launch_bounds__(256) void renorm_kernel(float* __restrict__ attn)
{
    const int idx = blockIdx.x * blockDim.x + threadIdx.x;  // over B*NQ
    if (idx >= BQ * NQ) return;
    const int b = idx / NQ, n = idx % NQ;
    float* p = attn + (size_t)b * KQ * NQ + n;
    float s = 0.f;
    #pragma unroll
    for (int k = 0; k < KQ; k++) s += p[(size_t)k * NQ];
    const float inv = 1.f / (1e-9f + s);
    #pragma unroll
    for (int k = 0; k < KQ; k++) p[(size_t)k * NQ] *= inv;
}

// ---------------------------------------------------------------------------
// Rank: per contiguous 512-chunk, thr = 256th largest (bitonic), scale.
// ---------------------------------------------------------------------------
__global__ __launch_bounds__(256) void rank_kernel(float* __restrict__ y2)
{
    const int row = blockIdx.x;
    float* p = y2 + (size_t)row * 512;
    const int tid = threadIdx.x;
    __shared__ float s[512];

    const float v0 = p[tid];
    const float v1 = p[tid + 256];
    s[tid] = v0; s[tid + 256] = v1;
    __syncthreads();

    for (int k = 2; k <= 512; k <<= 1) {
        for (int j = k >> 1; j > 0; j >>= 1) {
            int i = ((tid & ~(j - 1)) << 1) | (tid & (j - 1));
            int partner = i | j;
            bool up = ((i & k) == 0);
            float a = s[i], bb = s[partner];
            if ((a > bb) == up) { s[i] = bb; s[partner] = a; }
            __syncthreads();
        }
    }
    const float thr = s[256];
    p[tid]       = (v0 < thr) ? 0.75f * v0 : 1.25f * v0;
    p[tid + 256] = (v1 < thr) ? 0.75f * v1 : 1.25f * v1;
}

// ---------------------------------------------------------------------------
// Launch
// ---------------------------------------------------------------------------
extern "C" void kernel_launch(void* const* d_in, const int* in_sizes, int n_in,
                              void* d_out, int out_size)
{
    const float* x  = (const float*)d_in[0];  // (B, C, H, W)
    const float* w1 = (const float*)d_in[1];  // (C, C)
    const float* b1 = (const float*)d_in[2];  // (C,)
    const float* l0 = (const float*)d_in[3];  // (K, C)
    const float* l1 = (const float*)d_in[4];  // (C, K)
    const float* w2 = (const float*)d_in[5];  // (C, C)
    float* out = (float*)d_out;

    void *yp_, *ap_, *y2p_, *w1t_, *w2t_, *l0t_, *l1t_;
    cudaGetSymbolAddress(&yp_, g_y);
    cudaGetSymbolAddress(&ap_, g_attn);
    cudaGetSymbolAddress(&y2p_, g_y2);
    cudaGetSymbolAddress(&w1t_, g_w1T);
    cudaGetSymbolAddress(&w2t_, g_w2T);
    cudaGetSymbolAddress(&l0t_, g_l0T);
    cudaGetSymbolAddress(&l1t_, g_l1T);
    float* y    = (float*)yp_;
    float* attn = (float*)ap_;
    float* y2   = (float*)y2p_;
    float* w1T  = (float*)w1t_;
    float* w2T  = (float*)w2t_;
    float* l0T  = (float*)l0t_;
    float* l1T  = (float*)l1t_;

    // Weight transposes
    transpose_kernel<<<dim3(CQ/32, CQ/32), dim3(32, 8)>>>(w1, w1T, CQ, CQ);
    transpose_kernel<<<dim3(CQ/32, CQ/32), dim3(32, 8)>>>(w2, w2T, CQ, CQ);
    transpose_kernel<<<dim3(CQ/32, KQ/32), dim3(32, 8)>>>(l0, l0T, KQ, CQ);
    transpose_kernel<<<dim3(KQ/32, CQ/32), dim3(32, 8)>>>(l1, l1T, CQ, KQ);

    // conv1: y = W1 @ x + b1
    gemm_nt_kernel<CQ, CQ, NQ, 128, 128, 16, 8, 8, 1>
        <<<dim3(NQ / 128, CQ / 128, BQ), 256>>>(w1T, x, b1, nullptr, y);

    // lin0: attn = L0 @ y
    gemm_nt_kernel<KQ, CQ, NQ, 64, 128, 16, 4, 8, 0>
        <<<dim3(NQ / 128, 1, BQ), 256>>>(l0T, y, nullptr, nullptr, attn);

    // softmax over tokens
    softmax_kernel<<<BQ * KQ, 256>>>(attn);

    // L1 renorm over latent dim
    renorm_kernel<<<(BQ * NQ) / 256, 256>>>(attn);

    // lin1: y2 = L1 @ attn
    gemm_nt_kernel<CQ, KQ, NQ, 128, 128, 16, 8, 8, 0>
        <<<dim3(NQ / 128, CQ / 128, BQ), 256>>>(l1T, attn, nullptr, nullptr, y2);

    // rank
    rank_kernel<<<(BQ * CQ * NQ) / 512, 256>>>(y2);

    // conv2 + relu + residual + relu  (B operand = ranked y2, resid = x)
    gemm_nt_kernel<CQ, CQ, NQ, 128, 128, 16, 8, 8, 2>
        <<<dim3(NQ / 128, CQ / 128, BQ), 256>>>(w2T, y2, nullptr, x, out);
}

// round 3
// speedup vs baseline: 1.8413x; 1.4140x over previous
#include <cuda_runtime.h>
#include <math.h>

// Problem dims
#define BQ 16
#define CQ 512
#define NQ 4096   // H*W
#define KQ 64

// Scratch (allocation-free rule: device globals)
__device__ __align__(128) float g_attn[BQ * KQ * NQ];  // attention logits / probs
__device__ __align__(128) float g_y2  [BQ * CQ * NQ];  // lin1 output / ranked
__device__ __align__(128) float g_w2T [CQ * CQ];       // conv2 weight, transposed [c][o]
__device__ __align__(128) float g_l1T [KQ * CQ];       // lin1 weight, transposed [k][c]
__device__ __align__(128) float g_w01T[CQ * KQ];       // fused (L0@W1) transposed: [c][k]
__device__ __align__(128) float g_b01 [KQ];            // fused bias L0@b1

// ---------------------------------------------------------------------------
// cp.async helpers (16B, global -> shared)
// ---------------------------------------------------------------------------
__device__ __forceinline__ void cpa16(void* smem_dst, const void* gmem_src) {
    unsigned sa = (unsigned)__cvta_generic_to_shared(smem_dst);
    asm volatile("cp.async.ca.shared.global [%0], [%1], 16;" :: "r"(sa), "l"(gmem_src));
}
__device__ __forceinline__ void cpa_commit() {
    asm volatile("cp.async.commit_group;" ::: "memory");
}
__device__ __forceinline__ void cpa_wait0() {
    asm volatile("cp.async.wait_group 0;" ::: "memory");
}

// ---------------------------------------------------------------------------
// Transpose: AT[k][m] = A[m][k].  M, K multiples of 32.
// ---------------------------------------------------------------------------
__global__ __launch_bounds__(256) void transpose_kernel(
    const float* __restrict__ A, float* __restrict__ AT, int M, int K)
{
    __shared__ float t[32][33];
    const int m0 = blockIdx.y * 32, k0 = blockIdx.x * 32;
    const int x = threadIdx.x, y = threadIdx.y;   // block (32, 8)
    #pragma unroll
    for (int yy = y; yy < 32; yy += 8)
        t[yy][x] = A[(size_t)(m0 + yy) * K + k0 + x];
    __syncthreads();
    #pragma unroll
    for (int yy = y; yy < 32; yy += 8)
        AT[(size_t)(k0 + yy) * M + m0 + x] = t[x][yy];
}

// ---------------------------------------------------------------------------
// Weight fusion: W01T[c][k] = sum_o W1[o][c] * L0[k][o]   (512 x 64 out)
//                b01[k]     = sum_o L0[k][o] * b1[o]
// Tiled over o with shared staging; block (16,16), grid (C/16, K/16).
// ---------------------------------------------------------------------------
__global__ __launch_bounds__(256) void fuse_w01_kernel(
    const float* __restrict__ w1,   // (C_out=512, C_in=512) row-major
    const float* __restrict__ l0,   // (K=64, C=512) row-major
    const float* __restrict__ b1,   // (512,)
    float* __restrict__ w01T,       // (C_in=512, K=64)
    float* __restrict__ b01)        // (64,)
{
    __shared__ float sw[16][17];    // w1[o-tile][c-tile]
    __shared__ float sl[16][17];    // l0[k-tile][o-tile]
    const int c0 = blockIdx.x * 16, k0 = blockIdx.y * 16;
    const int tx = threadIdx.x, ty = threadIdx.y;   // (16,16)
    float acc = 0.f;
    for (int o0 = 0; o0 < CQ; o0 += 16) {
        sw[ty][tx] = w1[(size_t)(o0 + ty) * CQ + c0 + tx];
        sl[ty][tx] = l0[(size_t)(k0 + ty) * CQ + o0 + tx];
        __syncthreads();
        #pragma unroll
        for (int o = 0; o < 16; o++)
            acc += sw[o][tx] * sl[ty][o];
        __syncthreads();
    }
    w01T[(size_t)(c0 + tx) * KQ + k0 + ty] = acc;

    // bias: first block row handles b01 (K=64 values)
    if (blockIdx.x == 0 && tx == 0) {
        const int k = k0 + ty;
        float s = 0.f;
        for (int o = 0; o < CQ; o++) s += l0[(size_t)k * CQ + o] * b1[o];
        b01[k] = s;
    }
}

// ---------------------------------------------------------------------------
// SGEMM-NT: Out[b][m][n] = sum_k AT[k][m] * Bm[b][k][n]  (+epilogue)
// AT row-major Kc x M (transposed weight, shared across batch).
// Bm row-major Kc x Nn per batch. Double-buffered cp.async pipeline.
// EPI: 0 = plain store, 1 = +bias[m], 2 = relu -> +resid[b][m][n] -> relu
// ---------------------------------------------------------------------------
template<int M, int Kc, int Nn, int BM, int BN, int BK, int TM, int TN, int EPI>
__global__ __launch_bounds__((BM/TM)*(BN/TN))
void gemm_nt_kernel(const float* __restrict__ AT,
                    const float* __restrict__ Bm,
                    const float* __restrict__ bias,
                    const float* __restrict__ resid,
                    float* __restrict__ Out)
{
    constexpr int THREADS = (BM/TM)*(BN/TN);
    __shared__ float As[2][BK][BM];
    __shared__ float Bs[2][BK][BN];

    const int b   = blockIdx.z;
    const int bm0 = blockIdx.y * BM;
    const int bn0 = blockIdx.x * BN;
    const float* Bp = Bm + (size_t)b * Kc * Nn;
    float*       Op = Out + (size_t)b * M * Nn;

    const int tid = threadIdx.x;
    const int tx  = tid % (BN/TN);
    const int ty  = tid / (BN/TN);

    float acc[TM][TN];
    #pragma unroll
    for (int i = 0; i < TM; i++)
        #pragma unroll
        for (int j = 0; j < TN; j++) acc[i][j] = 0.f;

    auto load_tile = [&](int k0, int s) {
        #pragma unroll
        for (int i = tid; i < BK*BM/4; i += THREADS) {
            int k = (i*4) / BM, m = (i*4) % BM;
            cpa16(&As[s][k][m], &AT[(size_t)(k0 + k) * M + bm0 + m]);
        }
        #pragma unroll
        for (int i = tid; i < BK*BN/4; i += THREADS) {
            int k = (i*4) / BN, n = (i*4) % BN;
            cpa16(&Bs[s][k][n], &Bp[(size_t)(k0 + k) * Nn + bn0 + n]);
        }
        cpa_commit();
    };

    constexpr int NT = Kc / BK;
    load_tile(0, 0);

    for (int t = 0; t < NT; t++) {
        cpa_wait0();
        __syncthreads();
        if (t + 1 < NT) load_tile((t + 1) * BK, (t + 1) & 1);

        const int s = t & 1;
        float a[2][TM], bb[2][TN];
        #pragma unroll
        for (int v = 0; v < TM; v += 4)
            *reinterpret_cast<float4*>(&a[0][v]) =
                *reinterpret_cast<const float4*>(&As[s][0][ty*TM + v]);
        #pragma unroll
        for (int v = 0; v < TN; v += 4)
            *reinterpret_cast<float4*>(&bb[0][v]) =
                *reinterpret_cast<const float4*>(&Bs[s][0][tx*TN + v]);

        #pragma unroll
        for (int k = 0; k < BK; k++) {
            if (k + 1 < BK) {
                #pragma unroll
                for (int v = 0; v < TM; v += 4)
                    *reinterpret_cast<float4*>(&a[(k+1)&1][v]) =
                        *reinterpret_cast<const float4*>(&As[s][k+1][ty*TM + v]);
                #pragma unroll
                for (int v = 0; v < TN; v += 4)
                    *reinterpret_cast<float4*>(&bb[(k+1)&1][v]) =
                        *reinterpret_cast<const float4*>(&Bs[s][k+1][tx*TN + v]);
            }
            const int c = k & 1;
            #pragma unroll
            for (int i = 0; i < TM; i++)
                #pragma unroll
                for (int j = 0; j < TN; j++)
                    acc[i][j] += a[c][i] * bb[c][j];
        }
    }

    #pragma unroll
    for (int i = 0; i < TM; i++) {
        const int m = bm0 + ty * TM + i;
        float bval = 0.f;
        if (EPI == 1) bval = bias[m];
        #pragma unroll
        for (int j = 0; j < TN; j += 4) {
            const int n = bn0 + tx * TN + j;
            float vv[4];
            #pragma unroll
            for (int u = 0; u < 4; u++) vv[u] = acc[i][j + u];
            if (EPI == 1) {
                #pragma unroll
                for (int u = 0; u < 4; u++) vv[u] += bval;
            }
            if (EPI == 2) {
                float4 r = *reinterpret_cast<const float4*>(
                    &resid[(size_t)b * M * Nn + (size_t)m * Nn + n]);
                vv[0] = fmaxf(fmaxf(vv[0], 0.f) + r.x, 0.f);
                vv[1] = fmaxf(fmaxf(vv[1], 0.f) + r.y, 0.f);
                vv[2] = fmaxf(fmaxf(vv[2], 0.f) + r.z, 0.f);
                vv[3] = fmaxf(fmaxf(vv[3], 0.f) + r.w, 0.f);
            }
            float4 o; o.x = vv[0]; o.y = vv[1]; o.z = vv[2]; o.w = vv[3];
            *reinterpret_cast<float4*>(&Op[(size_t)m * Nn + n]) = o;
        }
    }
}

// ---------------------------------------------------------------------------
// Softmax over the token axis (length NQ) for each (b, k) row. 256 threads.
// ---------------------------------------------------------------------------
__global__ __launch_bounds__(256) void softmax_kernel(float* __restrict__ attn)
{
    const int row = blockIdx.x;                 // 0 .. B*K-1
    float* p = attn + (size_t)row * NQ;
    const int tid = threadIdx.x;
    __shared__ float red[256];

    float v[NQ / 256];
    float m = -INFINITY;
    #pragma unroll
    for (int i = 0; i < NQ / 256; i++) {
        v[i] = p[tid + i * 256];
        m = fmaxf(m, v[i]);
    }
    red[tid] = m; __syncthreads();
    for (int s = 128; s > 0; s >>= 1) {
        if (tid < s) red[tid] = fmaxf(red[tid], red[tid + s]);
        __syncthreads();
    }
    m = red[0]; __syncthreads();

    float s = 0.f;
    #pragma unroll
    for (int i = 0; i < NQ / 256; i++) {
        v[i] = expf(v[i] - m);
        s += v[i];
    }
    red[tid] = s; __syncthreads();
    for (int st = 128; st > 0; st >>= 1) {
        if (tid < st) red[tid] += red[tid + st];
        __syncthreads();
    }
    const float inv = 1.f / red[0];
    #pragma unroll
    for (int i = 0; i < NQ / 256; i++) p[tid + i * 256] = v[i] * inv;
}

// ---------------------------------------------------------------------------
// L1 renorm over latent axis K for each (b, n)
// ---------------------------------------------------------------------------
__global__ __launch_bounds__(256) void renorm_kernel(float* __restrict__ attn)
{
    const int idx = blockIdx.x * blockDim.x + threadIdx.x;  // over B*NQ
    if (idx >= BQ * NQ) return;
    const int b = idx / NQ, n = idx % NQ;
    float* p = attn + (size_t)b * KQ * NQ + n;
    float s = 0.f;
    #pragma unroll
    for (int k = 0; k < KQ; k++) s += p[(size_t)k * NQ];
    const float inv = 1.f / (1e-9f + s);
    #pragma unroll
    for (int k = 0; k < KQ; k++) p[(size_t)k * NQ] *= inv;
}

// ---------------------------------------------------------------------------
// Rank: per contiguous 512-chunk, thr = 256th largest (bitonic), scale.
// ---------------------------------------------------------------------------
__global__ __launch_bounds__(256) void rank_kernel(float* __restrict__ y2)
{
    const int row = blockIdx.x;
    float* p = y2 + (size_t)row * 512;
    const int tid = threadIdx.x;
    __shared__ float s[512];

    const float v0 = p[tid];
    const float v1 = p[tid + 256];
    s[tid] = v0; s[tid + 256] = v1;
    __syncthreads();

    for (int k = 2; k <= 512; k <<= 1) {
        for (int j = k >> 1; j > 0; j >>= 1) {
            int i = ((tid & ~(j - 1)) << 1) | (tid & (j - 1));
            int partner = i | j;
            bool up = ((i & k) == 0);
            float a = s[i], bb = s[partner];
            if ((a > bb) == up) { s[i] = bb; s[partner] = a; }
            __syncthreads();
        }
    }
    const float thr = s[256];
    p[tid]       = (v0 < thr) ? 0.75f * v0 : 1.25f * v0;
    p[tid + 256] = (v1 < thr) ? 0.75f * v1 : 1.25f * v1;
}

// ---------------------------------------------------------------------------
// Launch
// ---------------------------------------------------------------------------
extern "C" void kernel_launch(void* const* d_in, const int* in_sizes, int n_in,
                              void* d_out, int out_size)
{
    const float* x  = (const float*)d_in[0];  // (B, C, H, W)
    const float* w1 = (const float*)d_in[1];  // (C, C)
    const float* b1 = (const float*)d_in[2];  // (C,)
    const float* l0 = (const float*)d_in[3];  // (K, C)
    const float* l1 = (const float*)d_in[4];  // (C, K)
    const float* w2 = (const float*)d_in[5];  // (C, C)
    float* out = (float*)d_out;

    void *ap_, *y2p_, *w2t_, *l1t_, *w01_, *b01_;
    cudaGetSymbolAddress(&ap_, g_attn);
    cudaGetSymbolAddress(&y2p_, g_y2);
    cudaGetSymbolAddress(&w2t_, g_w2T);
    cudaGetSymbolAddress(&l1t_, g_l1T);
    cudaGetSymbolAddress(&w01_, g_w01T);
    cudaGetSymbolAddress(&b01_, g_b01);
    float* attn = (float*)ap_;
    float* y2   = (float*)y2p_;
    float* w2T  = (float*)w2t_;
    float* l1T  = (float*)l1t_;
    float* w01T = (float*)w01_;
    float* b01  = (float*)b01_;

    // Weight prep: w2 transpose, l1 transpose, fused (L0@W1) weight + bias
    transpose_kernel<<<dim3(CQ/32, CQ/32), dim3(32, 8)>>>(w2, w2T, CQ, CQ);
    transpose_kernel<<<dim3(KQ/32, CQ/32), dim3(32, 8)>>>(l1, l1T, CQ, KQ);
    fuse_w01_kernel<<<dim3(CQ/16, KQ/16), dim3(16, 16)>>>(w1, l0, b1, w01T, b01);

    // Fused conv1+lin0: attn = (L0@W1) @ x + (L0@b1)
    gemm_nt_kernel<KQ, CQ, NQ, 64, 128, 16, 4, 8, 1>
        <<<dim3(NQ / 128, 1, BQ), 256>>>(w01T, x, b01, nullptr, attn);

    // softmax over tokens
    softmax_kernel<<<BQ * KQ, 256>>>(attn);

    // L1 renorm over latent dim
    renorm_kernel<<<(BQ * NQ) / 256, 256>>>(attn);

    // lin1: y2 = L1 @ attn
    gemm_nt_kernel<CQ, KQ, NQ, 128, 128, 16, 8, 8, 0>
        <<<dim3(NQ / 128, CQ / 128, BQ), 256>>>(l1T, attn, nullptr, nullptr, y2);

    // rank
    rank_kernel<<<(BQ * CQ * NQ) / 512, 256>>>(y2);

    // conv2 + relu + residual + relu  (B operand = ranked y2, resid = x)
    gemm_nt_kernel<CQ, CQ, NQ, 128, 128, 16, 8, 8, 2>
        <<<dim3(NQ / 128, CQ / 128, BQ), 256>>>(w2T, y2, nullptr, x, out);
}

// round 4
// speedup vs baseline: 2.5447x; 1.3820x over previous
#include <cuda_runtime.h>
#include <math.h>
#include <stdint.h>

// Problem dims
#define BQ 16
#define CQ 512
#define NQ 4096   // H*W
#define KQ 64

// Scratch (allocation-free rule: device globals)
__device__ __align__(128) float g_attn[BQ * KQ * NQ];  // attention logits / probs
__device__ __align__(128) float g_y2  [BQ * CQ * NQ];  // lin1 output / ranked (tf32-rounded after rank)
__device__ __align__(128) float g_w2T [CQ * CQ];       // conv2 weight, transposed [c][o], tf32-rounded
__device__ __align__(128) float g_l1T [KQ * CQ];       // lin1 weight, transposed [k][c] (full fp32)
__device__ __align__(128) float g_w01T[CQ * KQ];       // fused (L0@W1) transposed: [c][k]
__device__ __align__(128) float g_b01 [KQ];            // fused bias L0@b1

// ---------------------------------------------------------------------------
// helpers
// ---------------------------------------------------------------------------
__device__ __forceinline__ void cpa16(void* smem_dst, const void* gmem_src) {
    unsigned sa = (unsigned)__cvta_generic_to_shared(smem_dst);
    asm volatile("cp.async.ca.shared.global [%0], [%1], 16;" :: "r"(sa), "l"(gmem_src));
}
__device__ __forceinline__ void cpa_commit() {
    asm volatile("cp.async.commit_group;" ::: "memory");
}
__device__ __forceinline__ void cpa_wait0() {
    asm volatile("cp.async.wait_group 0;" ::: "memory");
}
__device__ __forceinline__ float to_tf32(float x) {
    float r;
    asm("cvt.rna.tf32.f32 %0, %1;" : "=f"(r) : "f"(x));
    return r;
}

// ---------------------------------------------------------------------------
// Transpose: AT[k][m] = A[m][k]. Optional tf32 rounding of values.
// ---------------------------------------------------------------------------
template<bool TF32>
__global__ __launch_bounds__(256) void transpose_kernel(
    const float* __restrict__ A, float* __restrict__ AT, int M, int K)
{
    __shared__ float t[32][33];
    const int m0 = blockIdx.y * 32, k0 = blockIdx.x * 32;
    const int x = threadIdx.x, y = threadIdx.y;   // block (32, 8)
    #pragma unroll
    for (int yy = y; yy < 32; yy += 8) {
        float v = A[(size_t)(m0 + yy) * K + k0 + x];
        t[yy][x] = TF32 ? to_tf32(v) : v;
    }
    __syncthreads();
    #pragma unroll
    for (int yy = y; yy < 32; yy += 8)
        AT[(size_t)(k0 + yy) * M + m0 + x] = t[x][yy];
}

// ---------------------------------------------------------------------------
// Weight fusion: W01T[c][k] = sum_o W1[o][c] * L0[k][o], b01[k] = L0@b1
// ---------------------------------------------------------------------------
__global__ __launch_bounds__(256) void fuse_w01_kernel(
    const float* __restrict__ w1, const float* __restrict__ l0,
    const float* __restrict__ b1, float* __restrict__ w01T, float* __restrict__ b01)
{
    __shared__ float sw[16][17];
    __shared__ float sl[16][17];
    const int c0 = blockIdx.x * 16, k0 = blockIdx.y * 16;
    const int tx = threadIdx.x, ty = threadIdx.y;
    float acc = 0.f;
    for (int o0 = 0; o0 < CQ; o0 += 16) {
        sw[ty][tx] = w1[(size_t)(o0 + ty) * CQ + c0 + tx];
        sl[ty][tx] = l0[(size_t)(k0 + ty) * CQ + o0 + tx];
        __syncthreads();
        #pragma unroll
        for (int o = 0; o < 16; o++)
            acc += sw[o][tx] * sl[ty][o];
        __syncthreads();
    }
    w01T[(size_t)(c0 + tx) * KQ + k0 + ty] = acc;
    if (blockIdx.x == 0 && tx == 0) {
        const int k = k0 + ty;
        float s = 0.f;
        for (int o = 0; o < CQ; o++) s += l0[(size_t)k * CQ + o] * b1[o];
        b01[k] = s;
    }
}

// ---------------------------------------------------------------------------
// fp32 SGEMM-NT (kept for pre-rank GEMMs; precision-critical path)
// ---------------------------------------------------------------------------
template<int M, int Kc, int Nn, int BM, int BN, int BK, int TM, int TN, int EPI>
__global__ __launch_bounds__((BM/TM)*(BN/TN))
void gemm_nt_kernel(const float* __restrict__ AT,
                    const float* __restrict__ Bm,
                    const float* __restrict__ bias,
                    const float* __restrict__ resid,
                    float* __restrict__ Out)
{
    constexpr int THREADS = (BM/TM)*(BN/TN);
    __shared__ float As[2][BK][BM];
    __shared__ float Bs[2][BK][BN];

    const int b   = blockIdx.z;
    const int bm0 = blockIdx.y * BM;
    const int bn0 = blockIdx.x * BN;
    const float* Bp = Bm + (size_t)b * Kc * Nn;
    float*       Op = Out + (size_t)b * M * Nn;

    const int tid = threadIdx.x;
    const int tx  = tid % (BN/TN);
    const int ty  = tid / (BN/TN);

    float acc[TM][TN];
    #pragma unroll
    for (int i = 0; i < TM; i++)
        #pragma unroll
        for (int j = 0; j < TN; j++) acc[i][j] = 0.f;

    auto load_tile = [&](int k0, int s) {
        #pragma unroll
        for (int i = tid; i < BK*BM/4; i += THREADS) {
            int k = (i*4) / BM, m = (i*4) % BM;
            cpa16(&As[s][k][m], &AT[(size_t)(k0 + k) * M + bm0 + m]);
        }
        #pragma unroll
        for (int i = tid; i < BK*BN/4; i += THREADS) {
            int k = (i*4) / BN, n = (i*4) % BN;
            cpa16(&Bs[s][k][n], &Bp[(size_t)(k0 + k) * Nn + bn0 + n]);
        }
        cpa_commit();
    };

    constexpr int NT = Kc / BK;
    load_tile(0, 0);

    for (int t = 0; t < NT; t++) {
        cpa_wait0();
        __syncthreads();
        if (t + 1 < NT) load_tile((t + 1) * BK, (t + 1) & 1);

        const int s = t & 1;
        float a[2][TM], bb[2][TN];
        #pragma unroll
        for (int v = 0; v < TM; v += 4)
            *reinterpret_cast<float4*>(&a[0][v]) =
                *reinterpret_cast<const float4*>(&As[s][0][ty*TM + v]);
        #pragma unroll
        for (int v = 0; v < TN; v += 4)
            *reinterpret_cast<float4*>(&bb[0][v]) =
                *reinterpret_cast<const float4*>(&Bs[s][0][tx*TN + v]);

        #pragma unroll
        for (int k = 0; k < BK; k++) {
            if (k + 1 < BK) {
                #pragma unroll
                for (int v = 0; v < TM; v += 4)
                    *reinterpret_cast<float4*>(&a[(k+1)&1][v]) =
                        *reinterpret_cast<const float4*>(&As[s][k+1][ty*TM + v]);
                #pragma unroll
                for (int v = 0; v < TN; v += 4)
                    *reinterpret_cast<float4*>(&bb[(k+1)&1][v]) =
                        *reinterpret_cast<const float4*>(&Bs[s][k+1][tx*TN + v]);
            }
            const int c = k & 1;
            #pragma unroll
            for (int i = 0; i < TM; i++)
                #pragma unroll
                for (int j = 0; j < TN; j++)
                    acc[i][j] += a[c][i] * bb[c][j];
        }
    }

    #pragma unroll
    for (int i = 0; i < TM; i++) {
        const int m = bm0 + ty * TM + i;
        float bval = 0.f;
        if (EPI == 1) bval = bias[m];
        #pragma unroll
        for (int j = 0; j < TN; j += 4) {
            const int n = bn0 + tx * TN + j;
            float vv[4];
            #pragma unroll
            for (int u = 0; u < 4; u++) vv[u] = acc[i][j + u];
            if (EPI == 1) {
                #pragma unroll
                for (int u = 0; u < 4; u++) vv[u] += bval;
            }
            float4 o; o.x = vv[0]; o.y = vv[1]; o.z = vv[2]; o.w = vv[3];
            *reinterpret_cast<float4*>(&Op[(size_t)m * Nn + n]) = o;
        }
    }
}

// ---------------------------------------------------------------------------
// TF32 tensor-core GEMM for conv2 (post-rank, precision-tolerant).
// Out[b][m][n] = relu( relu( sum_c W2T[c][m]*y2[b][c][n] ) + x[b][m][n] )
// mma.sync.m16n8k8.tf32; BM=BN=128, BK=16, 8 warps (2m x 4n), warp tile 64x32.
// Smem XOR-swizzled: col_group(8 floats) ^= (k & 3)  -> conflict-free frags.
// ---------------------------------------------------------------------------
__device__ __forceinline__ void mma_tf32(float d[4], const uint32_t a[4],
                                         const uint32_t b[2]) {
    asm volatile(
        "mma.sync.aligned.m16n8k8.row.col.f32.tf32.tf32.f32 "
        "{%0,%1,%2,%3}, {%4,%5,%6,%7}, {%8,%9}, {%0,%1,%2,%3};"
        : "+f"(d[0]), "+f"(d[1]), "+f"(d[2]), "+f"(d[3])
        : "r"(a[0]), "r"(a[1]), "r"(a[2]), "r"(a[3]), "r"(b[0]), "r"(b[1]));
}

__global__ __launch_bounds__(256) void conv2_mma_kernel(
    const float* __restrict__ w2T,   // [512][512] tf32-rounded, [c][m]
    const float* __restrict__ y2,    // [B][512][4096] tf32-rounded
    const float* __restrict__ x,     // residual
    float* __restrict__ Out)
{
    constexpr int BM = 128, BN = 128, BK = 16;
    __shared__ float As[2][BK][BM];   // [k][m swizzled]
    __shared__ float Bs[2][BK][BN];   // [k][n swizzled]

    const int b   = blockIdx.z;
    const int bm0 = blockIdx.y * BM;
    const int bn0 = blockIdx.x * BN;
    const float* Bp = y2 + (size_t)b * CQ * NQ;

    const int tid  = threadIdx.x;
    const int wid  = tid / 32;
    const int lane = tid % 32;
    const int wm   = wid % 2;            // warp m index (0..1)
    const int wn   = wid / 2;            // warp n index (0..3)
    const int m0w  = wm * 64;
    const int n0w  = wn * 32;
    const int g4   = lane / 4;           // 0..7
    const int t4   = lane % 4;           // 0..3

    float acc[4][4][4];                  // [mtile][ntile][frag]
    #pragma unroll
    for (int i = 0; i < 4; i++)
        #pragma unroll
        for (int j = 0; j < 4; j++)
            #pragma unroll
            for (int u = 0; u < 4; u++) acc[i][j][u] = 0.f;

    // swizzled column: group of 8 floats XOR'd by (k & 3)
    auto swz = [](int col, int k) -> int {
        return (((col >> 3) ^ (k & 3)) << 3) | (col & 7);
    };

    // stage a BK x 128 tile (A from w2T stride 512, B from y2 stride 4096)
    auto load_tile = [&](int k0, int s) {
        // 16 rows x 32 chunks(16B) = 512 chunks; 2 per thread
        #pragma unroll
        for (int i = tid; i < 512; i += 256) {
            int k = i >> 5;                // /32
            int mc = (i & 31) << 2;        // chunk start col (mult of 4)
            cpa16(&As[s][k][swz(mc, k)], &w2T[(size_t)(k0 + k) * CQ + bm0 + mc]);
        }
        #pragma unroll
        for (int i = tid; i < 512; i += 256) {
            int k = i >> 5;
            int nc = (i & 31) << 2;
            cpa16(&Bs[s][k][swz(nc, k)], &Bp[(size_t)(k0 + k) * NQ + bn0 + nc]);
        }
        cpa_commit();
    };

    constexpr int NT = CQ / BK;          // 32
    load_tile(0, 0);

    for (int t = 0; t < NT; t++) {
        cpa_wait0();
        __syncthreads();
        if (t + 1 < NT) load_tile((t + 1) * BK, (t + 1) & 1);
        const int s = t & 1;

        #pragma unroll
        for (int ks = 0; ks < BK / 8; ks++) {
            const int k8 = ks * 8;
            const int klo = k8 + t4;       // rows for a0/a1, b0
            const int khi = klo + 4;       // rows for a2/a3, b1
            uint32_t a[4][4], bb[4][2];
            #pragma unroll
            for (int mt = 0; mt < 4; mt++) {
                const int mr = m0w + mt * 16 + g4;
                a[mt][0] = __float_as_uint(As[s][klo][swz(mr,     t4)]);
                a[mt][1] = __float_as_uint(As[s][klo][swz(mr + 8, t4)]);
                a[mt][2] = __float_as_uint(As[s][khi][swz(mr,     t4)]);
                a[mt][3] = __float_as_uint(As[s][khi][swz(mr + 8, t4)]);
            }
            #pragma unroll
            for (int nt = 0; nt < 4; nt++) {
                const int nc = n0w + nt * 8 + g4;
                bb[nt][0] = __float_as_uint(Bs[s][klo][swz(nc, t4)]);
                bb[nt][1] = __float_as_uint(Bs[s][khi][swz(nc, t4)]);
            }
            #pragma unroll
            for (int mt = 0; mt < 4; mt++)
                #pragma unroll
                for (int nt = 0; nt < 4; nt++)
                    mma_tf32(acc[mt][nt], a[mt], bb[nt]);
        }
    }

    // Epilogue: relu(relu(acc) + x) -> Out. float2 stores (lanes 0-3 cover 32B).
    const float* Xp = x + (size_t)b * CQ * NQ;
    float*       Op = Out + (size_t)b * CQ * NQ;
    #pragma unroll
    for (int mt = 0; mt < 4; mt++) {
        #pragma unroll
        for (int nt = 0; nt < 4; nt++) {
            const int row0 = bm0 + m0w + mt * 16 + g4;
            const int col  = bn0 + n0w + nt * 8 + 2 * t4;
            #pragma unroll
            for (int half = 0; half < 2; half++) {
                const int row = row0 + half * 8;
                float2 r = *reinterpret_cast<const float2*>(&Xp[(size_t)row * NQ + col]);
                float v0 = fmaxf(fmaxf(acc[mt][nt][2*half + 0], 0.f) + r.x, 0.f);
                float v1 = fmaxf(fmaxf(acc[mt][nt][2*half + 1], 0.f) + r.y, 0.f);
                float2 o; o.x = v0; o.y = v1;
                *reinterpret_cast<float2*>(&Op[(size_t)row * NQ + col]) = o;
            }
        }
    }
}

// ---------------------------------------------------------------------------
// Softmax over token axis
// ---------------------------------------------------------------------------
__global__ __launch_bounds__(256) void softmax_kernel(float* __restrict__ attn)
{
    const int row = blockIdx.x;
    float* p = attn + (size_t)row * NQ;
    const int tid = threadIdx.x;
    __shared__ float red[256];

    float v[NQ / 256];
    float m = -INFINITY;
    #pragma unroll
    for (int i = 0; i < NQ / 256; i++) {
        v[i] = p[tid + i * 256];
        m = fmaxf(m, v[i]);
    }
    red[tid] = m; __syncthreads();
    for (int s = 128; s > 0; s >>= 1) {
        if (tid < s) red[tid] = fmaxf(red[tid], red[tid + s]);
        __syncthreads();
    }
    m = red[0]; __syncthreads();

    float s = 0.f;
    #pragma unroll
    for (int i = 0; i < NQ / 256; i++) {
        v[i] = expf(v[i] - m);
        s += v[i];
    }
    red[tid] = s; __syncthreads();
    for (int st = 128; st > 0; st >>= 1) {
        if (tid < st) red[tid] += red[tid + st];
        __syncthreads();
    }
    const float inv = 1.f / red[0];
    #pragma unroll
    for (int i = 0; i < NQ / 256; i++) p[tid + i * 256] = v[i] * inv;
}

// ---------------------------------------------------------------------------
// L1 renorm over latent axis K
// ---------------------------------------------------------------------------
__global__ __launch_bounds__(256) void renorm_kernel(float* __restrict__ attn)
{
    const int idx = blockIdx.x * blockDim.x + threadIdx.x;
    if (idx >= BQ * NQ) return;
    const int b = idx / NQ, n = idx % NQ;
    float* p = attn + (size_t)b * KQ * NQ + n;
    float s = 0.f;
    #pragma unroll
    for (int k = 0; k < KQ; k++) s += p[(size_t)k * NQ];
    const float inv = 1.f / (1e-9f + s);
    #pragma unroll
    for (int k = 0; k < KQ; k++) p[(size_t)k * NQ] *= inv;
}

// ---------------------------------------------------------------------------
// Rank: per contiguous 512-chunk, thr = 256th largest (bitonic), scale,
// then round to tf32 (consumed by tf32 conv2).
// ---------------------------------------------------------------------------
__global__ __launch_bounds__(256) void rank_kernel(float* __restrict__ y2)
{
    const int row = blockIdx.x;
    float* p = y2 + (size_t)row * 512;
    const int tid = threadIdx.x;
    __shared__ float s[512];

    const float v0 = p[tid];
    const float v1 = p[tid + 256];
    s[tid] = v0; s[tid + 256] = v1;
    __syncthreads();

    for (int k = 2; k <= 512; k <<= 1) {
        for (int j = k >> 1; j > 0; j >>= 1) {
            int i = ((tid & ~(j - 1)) << 1) | (tid & (j - 1));
            int partner = i | j;
            bool up = ((i & k) == 0);
            float a = s[i], bb = s[partner];
            if ((a > bb) == up) { s[i] = bb; s[partner] = a; }
            __syncthreads();
        }
    }
    const float thr = s[256];
    p[tid]       = to_tf32((v0 < thr) ? 0.75f * v0 : 1.25f * v0);
    p[tid + 256] = to_tf32((v1 < thr) ? 0.75f * v1 : 1.25f * v1);
}

// ---------------------------------------------------------------------------
// Launch
// ---------------------------------------------------------------------------
extern "C" void kernel_launch(void* const* d_in, const int* in_sizes, int n_in,
                              void* d_out, int out_size)
{
    const float* x  = (const float*)d_in[0];
    const float* w1 = (const float*)d_in[1];
    const float* b1 = (const float*)d_in[2];
    const float* l0 = (const float*)d_in[3];
    const float* l1 = (const float*)d_in[4];
    const float* w2 = (const float*)d_in[5];
    float* out = (float*)d_out;

    void *ap_, *y2p_, *w2t_, *l1t_, *w01_, *b01_;
    cudaGetSymbolAddress(&ap_, g_attn);
    cudaGetSymbolAddress(&y2p_, g_y2);
    cudaGetSymbolAddress(&w2t_, g_w2T);
    cudaGetSymbolAddress(&l1t_, g_l1T);
    cudaGetSymbolAddress(&w01_, g_w01T);
    cudaGetSymbolAddress(&b01_, g_b01);
    float* attn = (float*)ap_;
    float* y2   = (float*)y2p_;
    float* w2T  = (float*)w2t_;
    float* l1T  = (float*)l1t_;
    float* w01T = (float*)w01_;
    float* b01  = (float*)b01_;

    // Weight prep
    transpose_kernel<true ><<<dim3(CQ/32, CQ/32), dim3(32, 8)>>>(w2, w2T, CQ, CQ);  // tf32
    transpose_kernel<false><<<dim3(KQ/32, CQ/32), dim3(32, 8)>>>(l1, l1T, CQ, KQ);  // fp32
    fuse_w01_kernel<<<dim3(CQ/16, KQ/16), dim3(16, 16)>>>(w1, l0, b1, w01T, b01);

    // Fused conv1+lin0 (fp32): attn = (L0@W1) @ x + (L0@b1)
    gemm_nt_kernel<KQ, CQ, NQ, 64, 128, 16, 4, 8, 1>
        <<<dim3(NQ / 128, 1, BQ), 256>>>(w01T, x, b01, nullptr, attn);

    softmax_kernel<<<BQ * KQ, 256>>>(attn);
    renorm_kernel<<<(BQ * NQ) / 256, 256>>>(attn);

    // lin1 (fp32, precision-critical): y2 = L1 @ attn
    gemm_nt_kernel<CQ, KQ, NQ, 128, 128, 16, 8, 8, 0>
        <<<dim3(NQ / 128, CQ / 128, BQ), 256>>>(l1T, attn, nullptr, nullptr, y2);

    // rank (+ tf32 rounding of outputs)
    rank_kernel<<<(BQ * CQ * NQ) / 512, 256>>>(y2);

    // conv2 via tf32 tensor cores + fused relu/residual/relu
    conv2_mma_kernel<<<dim3(NQ / 128, CQ / 128, BQ), 256>>>(w2T, y2, x, out);
}

// round 5
// speedup vs baseline: 2.7975x; 1.0994x over previous
#include <cuda_runtime.h>
#include <cuda_bf16.h>
#include <math.h>
#include <stdint.h>

// Problem dims
#define BQ 16
#define CQ 512
#define NQ 4096   // H*W
#define KQ 64

// Scratch (allocation-free rule: device globals)
__device__ __align__(128) float         g_attn[BQ * KQ * NQ]; // attn logits/probs
__device__ __align__(128) float         g_y2  [BQ * CQ * NQ]; // lin1 output (fp32)
__device__ __align__(128) __nv_bfloat16 g_y2h [BQ * CQ * NQ]; // ranked y2, bf16
__device__ __align__(128) __nv_bfloat16 g_w2h [CQ * CQ];      // conv2 weight [c][o] bf16
__device__ __align__(128) float         g_l1T [KQ * CQ];      // lin1 weight [k][c] fp32
__device__ __align__(128) float         g_w01T[CQ * KQ];      // fused (L0@W1)^T [c][k]
__device__ __align__(128) float         g_b01 [KQ];           // fused bias L0@b1

// ---------------------------------------------------------------------------
// helpers
// ---------------------------------------------------------------------------
__device__ __forceinline__ void cpa16(void* smem_dst, const void* gmem_src) {
    unsigned sa = (unsigned)__cvta_generic_to_shared(smem_dst);
    asm volatile("cp.async.ca.shared.global [%0], [%1], 16;" :: "r"(sa), "l"(gmem_src));
}
__device__ __forceinline__ void cpa_commit() {
    asm volatile("cp.async.commit_group;" ::: "memory");
}
__device__ __forceinline__ void cpa_wait0() {
    asm volatile("cp.async.wait_group 0;" ::: "memory");
}
__device__ __forceinline__ uint32_t smem_u32(const void* p) {
    return (uint32_t)__cvta_generic_to_shared(p);
}

// ---------------------------------------------------------------------------
// Transpose fp32: AT[k][m] = A[m][k]
// ---------------------------------------------------------------------------
__global__ __launch_bounds__(256) void transpose_kernel(
    const float* __restrict__ A, float* __restrict__ AT, int M, int K)
{
    __shared__ float t[32][33];
    const int m0 = blockIdx.y * 32, k0 = blockIdx.x * 32;
    const int x = threadIdx.x, y = threadIdx.y;
    #pragma unroll
    for (int yy = y; yy < 32; yy += 8)
        t[yy][x] = A[(size_t)(m0 + yy) * K + k0 + x];
    __syncthreads();
    #pragma unroll
    for (int yy = y; yy < 32; yy += 8)
        AT[(size_t)(k0 + yy) * M + m0 + x] = t[x][yy];
}

// Transpose + bf16 convert: AT[k][m] = bf16(A[m][k])
__global__ __launch_bounds__(256) void transpose_bf16_kernel(
    const float* __restrict__ A, __nv_bfloat16* __restrict__ AT, int M, int K)
{
    __shared__ float t[32][33];
    const int m0 = blockIdx.y * 32, k0 = blockIdx.x * 32;
    const int x = threadIdx.x, y = threadIdx.y;
    #pragma unroll
    for (int yy = y; yy < 32; yy += 8)
        t[yy][x] = A[(size_t)(m0 + yy) * K + k0 + x];
    __syncthreads();
    #pragma unroll
    for (int yy = y; yy < 32; yy += 8)
        AT[(size_t)(k0 + yy) * M + m0 + x] = __float2bfloat16_rn(t[x][yy]);
}

// ---------------------------------------------------------------------------
// Weight fusion: W01T[c][k] = sum_o W1[o][c] * L0[k][o], b01[k] = L0@b1
// ---------------------------------------------------------------------------
__global__ __launch_bounds__(256) void fuse_w01_kernel(
    const float* __restrict__ w1, const float* __restrict__ l0,
    const float* __restrict__ b1, float* __restrict__ w01T, float* __restrict__ b01)
{
    __shared__ float sw[16][17];
    __shared__ float sl[16][17];
    const int c0 = blockIdx.x * 16, k0 = blockIdx.y * 16;
    const int tx = threadIdx.x, ty = threadIdx.y;
    float acc = 0.f;
    for (int o0 = 0; o0 < CQ; o0 += 16) {
        sw[ty][tx] = w1[(size_t)(o0 + ty) * CQ + c0 + tx];
        sl[ty][tx] = l0[(size_t)(k0 + ty) * CQ + o0 + tx];
        __syncthreads();
        #pragma unroll
        for (int o = 0; o < 16; o++)
            acc += sw[o][tx] * sl[ty][o];
        __syncthreads();
    }
    w01T[(size_t)(c0 + tx) * KQ + k0 + ty] = acc;
    if (blockIdx.x == 0 && tx == 0) {
        const int k = k0 + ty;
        float s = 0.f;
        for (int o = 0; o < CQ; o++) s += l0[(size_t)k * CQ + o] * b1[o];
        b01[k] = s;
    }
}

// ---------------------------------------------------------------------------
// fp32 SGEMM-NT (pre-rank GEMMs; precision-critical path)
// ---------------------------------------------------------------------------
template<int M, int Kc, int Nn, int BM, int BN, int BK, int TM, int TN, int EPI>
__global__ __launch_bounds__((BM/TM)*(BN/TN))
void gemm_nt_kernel(const float* __restrict__ AT,
                    const float* __restrict__ Bm,
                    const float* __restrict__ bias,
                    float* __restrict__ Out)
{
    constexpr int THREADS = (BM/TM)*(BN/TN);
    __shared__ float As[2][BK][BM];
    __shared__ float Bs[2][BK][BN];

    const int b   = blockIdx.z;
    const int bm0 = blockIdx.y * BM;
    const int bn0 = blockIdx.x * BN;
    const float* Bp = Bm + (size_t)b * Kc * Nn;
    float*       Op = Out + (size_t)b * M * Nn;

    const int tid = threadIdx.x;
    const int tx  = tid % (BN/TN);
    const int ty  = tid / (BN/TN);

    float acc[TM][TN];
    #pragma unroll
    for (int i = 0; i < TM; i++)
        #pragma unroll
        for (int j = 0; j < TN; j++) acc[i][j] = 0.f;

    auto load_tile = [&](int k0, int s) {
        #pragma unroll
        for (int i = tid; i < BK*BM/4; i += THREADS) {
            int k = (i*4) / BM, m = (i*4) % BM;
            cpa16(&As[s][k][m], &AT[(size_t)(k0 + k) * M + bm0 + m]);
        }
        #pragma unroll
        for (int i = tid; i < BK*BN/4; i += THREADS) {
            int k = (i*4) / BN, n = (i*4) % BN;
            cpa16(&Bs[s][k][n], &Bp[(size_t)(k0 + k) * Nn + bn0 + n]);
        }
        cpa_commit();
    };

    constexpr int NT = Kc / BK;
    load_tile(0, 0);

    for (int t = 0; t < NT; t++) {
        cpa_wait0();
        __syncthreads();
        if (t + 1 < NT) load_tile((t + 1) * BK, (t + 1) & 1);

        const int s = t & 1;
        float a[2][TM], bb[2][TN];
        #pragma unroll
        for (int v = 0; v < TM; v += 4)
            *reinterpret_cast<float4*>(&a[0][v]) =
                *reinterpret_cast<const float4*>(&As[s][0][ty*TM + v]);
        #pragma unroll
        for (int v = 0; v < TN; v += 4)
            *reinterpret_cast<float4*>(&bb[0][v]) =
                *reinterpret_cast<const float4*>(&Bs[s][0][tx*TN + v]);

        #pragma unroll
        for (int k = 0; k < BK; k++) {
            if (k + 1 < BK) {
                #pragma unroll
                for (int v = 0; v < TM; v += 4)
                    *reinterpret_cast<float4*>(&a[(k+1)&1][v]) =
                        *reinterpret_cast<const float4*>(&As[s][k+1][ty*TM + v]);
                #pragma unroll
                for (int v = 0; v < TN; v += 4)
                    *reinterpret_cast<float4*>(&bb[(k+1)&1][v]) =
                        *reinterpret_cast<const float4*>(&Bs[s][k+1][tx*TN + v]);
            }
            const int c = k & 1;
            #pragma unroll
            for (int i = 0; i < TM; i++)
                #pragma unroll
                for (int j = 0; j < TN; j++)
                    acc[i][j] += a[c][i] * bb[c][j];
        }
    }

    #pragma unroll
    for (int i = 0; i < TM; i++) {
        const int m = bm0 + ty * TM + i;
        float bval = 0.f;
        if (EPI == 1) bval = bias[m];
        #pragma unroll
        for (int j = 0; j < TN; j += 4) {
            const int n = bn0 + tx * TN + j;
            float vv[4];
            #pragma unroll
            for (int u = 0; u < 4; u++) vv[u] = acc[i][j + u];
            if (EPI == 1) {
                #pragma unroll
                for (int u = 0; u < 4; u++) vv[u] += bval;
            }
            float4 o; o.x = vv[0]; o.y = vv[1]; o.z = vv[2]; o.w = vv[3];
            *reinterpret_cast<float4*>(&Op[(size_t)m * Nn + n]) = o;
        }
    }
}

// ---------------------------------------------------------------------------
// BF16 tensor-core conv2 (post-rank, precision-tolerant).
// Out[b][m][n] = relu( relu( sum_c W2[m][c]*y2[b][c][n] ) + x[b][m][n] )
// mma.sync.m16n8k16.bf16 + ldmatrix.x4.trans. BM=BN=128, BK=32.
// Smem [k][*] bf16, 16B-chunk XOR swizzle: chunk ^= (k & 7).
// ---------------------------------------------------------------------------
__device__ __forceinline__ void mma_bf16(float d[4], const uint32_t a[4],
                                         const uint32_t b0, const uint32_t b1) {
    asm volatile(
        "mma.sync.aligned.m16n8k16.row.col.f32.bf16.bf16.f32 "
        "{%0,%1,%2,%3}, {%4,%5,%6,%7}, {%8,%9}, {%0,%1,%2,%3};"
        : "+f"(d[0]), "+f"(d[1]), "+f"(d[2]), "+f"(d[3])
        : "r"(a[0]), "r"(a[1]), "r"(a[2]), "r"(a[3]), "r"(b0), "r"(b1));
}
__device__ __forceinline__ void ldsm_x4_trans(uint32_t r[4], uint32_t addr) {
    asm volatile(
        "ldmatrix.sync.aligned.m8n8.x4.trans.shared.b16 {%0,%1,%2,%3}, [%4];"
        : "=r"(r[0]), "=r"(r[1]), "=r"(r[2]), "=r"(r[3]) : "r"(addr));
}

__global__ __launch_bounds__(256) void conv2_bf16_kernel(
    const __nv_bfloat16* __restrict__ w2h,  // [c][m] bf16
    const __nv_bfloat16* __restrict__ y2h,  // [b][c][n] bf16
    const float* __restrict__ x,            // residual fp32
    float* __restrict__ Out)
{
    constexpr int BM = 128, BN = 128, BK = 32;
    __shared__ __nv_bfloat16 As[2][BK][BM];   // row = 256B = 16 chunks of 16B
    __shared__ __nv_bfloat16 Bs[2][BK][BN];

    const int b   = blockIdx.z;
    const int bm0 = blockIdx.y * BM;
    const int bn0 = blockIdx.x * BN;
    const __nv_bfloat16* Bp = y2h + (size_t)b * CQ * NQ;

    const int tid  = threadIdx.x;
    const int wid  = tid / 32;
    const int lane = tid % 32;
    const int wm   = wid % 2;              // 2 warps along m
    const int wn   = wid / 2;              // 4 warps along n
    const int m0w  = wm * 64;
    const int n0w  = wn * 32;
    const int g4   = lane / 4;
    const int t4   = lane % 4;

    float acc[4][4][4];
    #pragma unroll
    for (int i = 0; i < 4; i++)
        #pragma unroll
        for (int j = 0; j < 4; j++)
            #pragma unroll
            for (int u = 0; u < 4; u++) acc[i][j][u] = 0.f;

    // element-index swizzle within a 128-elem bf16 row (16 chunks of 8)
    auto swz = [](int e, int k) -> int {
        return ((((e >> 3) ^ (k & 7)) << 3) | (e & 7));
    };

    auto load_tile = [&](int k0, int s) {
        // A: 32 rows x 16 chunks = 512 chunk jobs
        #pragma unroll
        for (int i = tid; i < 512; i += 256) {
            int k = i >> 4, cc = i & 15;
            cpa16(&As[s][k][(cc ^ (k & 7)) << 3],
                  &w2h[(size_t)(k0 + k) * CQ + bm0 + (cc << 3)]);
        }
        #pragma unroll
        for (int i = tid; i < 512; i += 256) {
            int k = i >> 4, cc = i & 15;
            cpa16(&Bs[s][k][(cc ^ (k & 7)) << 3],
                  &Bp[(size_t)(k0 + k) * NQ + bn0 + (cc << 3)]);
        }
        cpa_commit();
    };

    constexpr int NT = CQ / BK;            // 16
    load_tile(0, 0);

    for (int t = 0; t < NT; t++) {
        cpa_wait0();
        __syncthreads();
        if (t + 1 < NT) load_tile((t + 1) * BK, (t + 1) & 1);
        const int s = t & 1;

        #pragma unroll
        for (int ks = 0; ks < BK; ks += 16) {
            // A fragments: 4 m16 tiles, ldmatrix.x4.trans each
            // lanes 0-7: (k ks+L,  m mbase), 8-15: (ks+L, mbase+8),
            // 16-23: (ks+8+L, mbase), 24-31: (ks+8+L, mbase+8)
            uint32_t a[4][4];
            const int l7  = lane & 7;
            const int kA  = ks + l7 + ((lane >> 4) << 3);
            const int mAo = (lane & 8);
            #pragma unroll
            for (int mt = 0; mt < 4; mt++) {
                const int mbase = m0w + mt * 16 + mAo;
                ldsm_x4_trans(a[mt], smem_u32(&As[s][kA][swz(mbase, kA)]));
            }
            // B fragments: 2 n16 pairs (each yields b-regs for two n8 tiles)
            // lanes 0-7: (ks+L, nbase), 8-15: (ks+8+L, nbase),
            // 16-23: (ks+L, nbase+8), 24-31: (ks+8+L, nbase+8)
            uint32_t bfr[2][4];
            const int kB  = ks + l7 + (lane & 8);
            const int nBo = ((lane >> 4) << 3);
            #pragma unroll
            for (int np = 0; np < 2; np++) {
                const int nbase = n0w + np * 16 + nBo;
                ldsm_x4_trans(bfr[np], smem_u32(&Bs[s][kB][swz(nbase, kB)]));
            }
            #pragma unroll
            for (int mt = 0; mt < 4; mt++)
                #pragma unroll
                for (int nt = 0; nt < 4; nt++) {
                    const uint32_t* bp = bfr[nt >> 1];
                    if ((nt & 1) == 0) mma_bf16(acc[mt][nt], a[mt], bp[0], bp[1]);
                    else               mma_bf16(acc[mt][nt], a[mt], bp[2], bp[3]);
                }
        }
    }

    // Epilogue: relu(relu(acc) + x) -> Out
    const float* Xp = x + (size_t)b * CQ * NQ;
    float*       Op = Out + (size_t)b * CQ * NQ;
    #pragma unroll
    for (int mt = 0; mt < 4; mt++) {
        #pragma unroll
        for (int nt = 0; nt < 4; nt++) {
            const int row0 = bm0 + m0w + mt * 16 + g4;
            const int col  = bn0 + n0w + nt * 8 + 2 * t4;
            #pragma unroll
            for (int half = 0; half < 2; half++) {
                const int row = row0 + half * 8;
                float2 r = *reinterpret_cast<const float2*>(&Xp[(size_t)row * NQ + col]);
                float v0 = fmaxf(fmaxf(acc[mt][nt][2*half + 0], 0.f) + r.x, 0.f);
                float v1 = fmaxf(fmaxf(acc[mt][nt][2*half + 1], 0.f) + r.y, 0.f);
                float2 o; o.x = v0; o.y = v1;
                *reinterpret_cast<float2*>(&Op[(size_t)row * NQ + col]) = o;
            }
        }
    }
}

// ---------------------------------------------------------------------------
// Softmax over token axis
// ---------------------------------------------------------------------------
__global__ __launch_bounds__(256) void softmax_kernel(float* __restrict__ attn)
{
    const int row = blockIdx.x;
    float* p = attn + (size_t)row * NQ;
    const int tid = threadIdx.x;
    __shared__ float red[256];

    float v[NQ / 256];
    float m = -INFINITY;
    #pragma unroll
    for (int i = 0; i < NQ / 256; i++) {
        v[i] = p[tid + i * 256];
        m = fmaxf(m, v[i]);
    }
    red[tid] = m; __syncthreads();
    for (int s = 128; s > 0; s >>= 1) {
        if (tid < s) red[tid] = fmaxf(red[tid], red[tid + s]);
        __syncthreads();
    }
    m = red[0]; __syncthreads();

    float s = 0.f;
    #pragma unroll
    for (int i = 0; i < NQ / 256; i++) {
        v[i] = expf(v[i] - m);
        s += v[i];
    }
    red[tid] = s; __syncthreads();
    for (int st = 128; st > 0; st >>= 1) {
        if (tid < st) red[tid] += red[tid + st];
        __syncthreads();
    }
    const float inv = 1.f / red[0];
    #pragma unroll
    for (int i = 0; i < NQ / 256; i++) p[tid + i * 256] = v[i] * inv;
}

// ---------------------------------------------------------------------------
// L1 renorm over latent axis K
// ---------------------------------------------------------------------------
__global__ __launch_bounds__(256) void renorm_kernel(float* __restrict__ attn)
{
    const int idx = blockIdx.x * blockDim.x + threadIdx.x;
    if (idx >= BQ * NQ) return;
    const int b = idx / NQ, n = idx % NQ;
    float* p = attn + (size_t)b * KQ * NQ + n;
    float s = 0.f;
    #pragma unroll
    for (int k = 0; k < KQ; k++) s += p[(size_t)k * NQ];
    const float inv = 1.f / (1e-9f + s);
    #pragma unroll
    for (int k = 0; k < KQ; k++) p[(size_t)k * NQ] *= inv;
}

// ---------------------------------------------------------------------------
// Rank: per contiguous 512-chunk, thr = 256th largest (bitonic, fp32),
// scale, write bf16 (consumed by bf16 conv2).
// ---------------------------------------------------------------------------
__global__ __launch_bounds__(256) void rank_kernel(
    const float* __restrict__ y2, __nv_bfloat16* __restrict__ y2h)
{
    const int row = blockIdx.x;
    const float* p = y2 + (size_t)row * 512;
    __nv_bfloat16* q = y2h + (size_t)row * 512;
    const int tid = threadIdx.x;
    __shared__ float s[512];

    const float v0 = p[tid];
    const float v1 = p[tid + 256];
    s[tid] = v0; s[tid + 256] = v1;
    __syncthreads();

    for (int k = 2; k <= 512; k <<= 1) {
        for (int j = k >> 1; j > 0; j >>= 1) {
            int i = ((tid & ~(j - 1)) << 1) | (tid & (j - 1));
            int partner = i | j;
            bool up = ((i & k) == 0);
            float a = s[i], bb = s[partner];
            if ((a > bb) == up) { s[i] = bb; s[partner] = a; }
            __syncthreads();
        }
    }
    const float thr = s[256];
    q[tid]       = __float2bfloat16_rn((v0 < thr) ? 0.75f * v0 : 1.25f * v0);
    q[tid + 256] = __float2bfloat16_rn((v1 < thr) ? 0.75f * v1 : 1.25f * v1);
}

// ---------------------------------------------------------------------------
// Launch
// ---------------------------------------------------------------------------
extern "C" void kernel_launch(void* const* d_in, const int* in_sizes, int n_in,
                              void* d_out, int out_size)
{
    const float* x  = (const float*)d_in[0];
    const float* w1 = (const float*)d_in[1];
    const float* b1 = (const float*)d_in[2];
    const float* l0 = (const float*)d_in[3];
    const float* l1 = (const float*)d_in[4];
    const float* w2 = (const float*)d_in[5];
    float* out = (float*)d_out;

    void *ap_, *y2p_, *y2h_, *w2h_, *l1t_, *w01_, *b01_;
    cudaGetSymbolAddress(&ap_, g_attn);
    cudaGetSymbolAddress(&y2p_, g_y2);
    cudaGetSymbolAddress(&y2h_, g_y2h);
    cudaGetSymbolAddress(&w2h_, g_w2h);
    cudaGetSymbolAddress(&l1t_, g_l1T);
    cudaGetSymbolAddress(&w01_, g_w01T);
    cudaGetSymbolAddress(&b01_, g_b01);
    float*         attn = (float*)ap_;
    float*         y2   = (float*)y2p_;
    __nv_bfloat16* y2h  = (__nv_bfloat16*)y2h_;
    __nv_bfloat16* w2h  = (__nv_bfloat16*)w2h_;
    float*         l1T  = (float*)l1t_;
    float*         w01T = (float*)w01_;
    float*         b01  = (float*)b01_;

    // Weight prep
    transpose_bf16_kernel<<<dim3(CQ/32, CQ/32), dim3(32, 8)>>>(w2, w2h, CQ, CQ);
    transpose_kernel<<<dim3(KQ/32, CQ/32), dim3(32, 8)>>>(l1, l1T, CQ, KQ);
    fuse_w01_kernel<<<dim3(CQ/16, KQ/16), dim3(16, 16)>>>(w1, l0, b1, w01T, b01);

    // Fused conv1+lin0 (fp32): attn = (L0@W1) @ x + (L0@b1)
    gemm_nt_kernel<KQ, CQ, NQ, 64, 128, 16, 4, 8, 1>
        <<<dim3(NQ / 128, 1, BQ), 256>>>(w01T, x, b01, attn);

    softmax_kernel<<<BQ * KQ, 256>>>(attn);
    renorm_kernel<<<(BQ * NQ) / 256, 256>>>(attn);

    // lin1 (fp32, precision-critical): y2 = L1 @ attn
    gemm_nt_kernel<CQ, KQ, NQ, 128, 128, 16, 8, 8, 0>
        <<<dim3(NQ / 128, CQ / 128, BQ), 256>>>(l1T, attn, nullptr, y2);

    // rank (fp32 threshold, bf16 output)
    rank_kernel<<<(BQ * CQ * NQ) / 512, 256>>>(y2, y2h);

    // conv2 via bf16 tensor cores + fused relu/residual/relu
    conv2_bf16_kernel<<<dim3(NQ / 128, CQ / 128, BQ), 256>>>(w2h, y2h, x, out);
}

// round 7
// speedup vs baseline: 5.1880x; 1.8545x over previous
#include <cuda_runtime.h>
#include <cuda_bf16.h>
#include <math.h>
#include <stdint.h>

// Problem dims
#define BQ 16
#define CQ 512
#define NQ 4096   // H*W
#define KQ 64

// Scratch (allocation-free rule: device globals)
__device__ __align__(128) float         g_attn[BQ * KQ * NQ]; // attn logits/probs
__device__ __align__(128) __nv_bfloat16 g_y2h [BQ * CQ * NQ]; // ranked y2, bf16
__device__ __align__(128) __nv_bfloat16 g_w2h [CQ * CQ];      // conv2 weight [c][o] bf16
__device__ __align__(128) float         g_l1T [KQ * CQ];      // lin1 weight [k][c] fp32
__device__ __align__(128) float         g_w01T[CQ * KQ];      // fused (L0@W1)^T [c][k]
__device__ __align__(128) float         g_b01 [KQ];           // fused bias L0@b1

// ---------------------------------------------------------------------------
// helpers
// ---------------------------------------------------------------------------
__device__ __forceinline__ void cpa16(void* smem_dst, const void* gmem_src) {
    unsigned sa = (unsigned)__cvta_generic_to_shared(smem_dst);
    asm volatile("cp.async.ca.shared.global [%0], [%1], 16;" :: "r"(sa), "l"(gmem_src));
}
__device__ __forceinline__ void cpa_commit() {
    asm volatile("cp.async.commit_group;" ::: "memory");
}
template<int N>
__device__ __forceinline__ void cpa_wait() {
    asm volatile("cp.async.wait_group %0;" :: "n"(N) : "memory");
}
__device__ __forceinline__ uint32_t smem_u32(const void* p) {
    return (uint32_t)__cvta_generic_to_shared(p);
}

// ---------------------------------------------------------------------------
// Transpose fp32: AT[k][m] = A[m][k]
// ---------------------------------------------------------------------------
__global__ __launch_bounds__(256) void transpose_kernel(
    const float* __restrict__ A, float* __restrict__ AT, int M, int K)
{
    __shared__ float t[32][33];
    const int m0 = blockIdx.y * 32, k0 = blockIdx.x * 32;
    const int x = threadIdx.x, y = threadIdx.y;
    #pragma unroll
    for (int yy = y; yy < 32; yy += 8)
        t[yy][x] = A[(size_t)(m0 + yy) * K + k0 + x];
    __syncthreads();
    #pragma unroll
    for (int yy = y; yy < 32; yy += 8)
        AT[(size_t)(k0 + yy) * M + m0 + x] = t[x][yy];
}

// Transpose + bf16 convert: AT[k][m] = bf16(A[m][k])
__global__ __launch_bounds__(256) void transpose_bf16_kernel(
    const float* __restrict__ A, __nv_bfloat16* __restrict__ AT, int M, int K)
{
    __shared__ float t[32][33];
    const int m0 = blockIdx.y * 32, k0 = blockIdx.x * 32;
    const int x = threadIdx.x, y = threadIdx.y;
    #pragma unroll
    for (int yy = y; yy < 32; yy += 8)
        t[yy][x] = A[(size_t)(m0 + yy) * K + k0 + x];
    __syncthreads();
    #pragma unroll
    for (int yy = y; yy < 32; yy += 8)
        AT[(size_t)(k0 + yy) * M + m0 + x] = __float2bfloat16_rn(t[x][yy]);
}

// ---------------------------------------------------------------------------
// Weight fusion: W01T[c][k] = sum_o W1[o][c] * L0[k][o], b01[k] = L0@b1
// ---------------------------------------------------------------------------
__global__ __launch_bounds__(256) void fuse_w01_kernel(
    const float* __restrict__ w1, const float* __restrict__ l0,
    const float* __restrict__ b1, float* __restrict__ w01T, float* __restrict__ b01)
{
    __shared__ float sw[16][17];
    __shared__ float sl[16][17];
    const int c0 = blockIdx.x * 16, k0 = blockIdx.y * 16;
    const int tx = threadIdx.x, ty = threadIdx.y;
    float acc = 0.f;
    for (int o0 = 0; o0 < CQ; o0 += 16) {
        sw[ty][tx] = w1[(size_t)(o0 + ty) * CQ + c0 + tx];
        sl[ty][tx] = l0[(size_t)(k0 + ty) * CQ + o0 + tx];
        __syncthreads();
        #pragma unroll
        for (int o = 0; o < 16; o++)
            acc += sw[o][tx] * sl[ty][o];
        __syncthreads();
    }
    w01T[(size_t)(c0 + tx) * KQ + k0 + ty] = acc;
    if (blockIdx.x == 0 && tx == 0) {
        const int k = k0 + ty;
        float s = 0.f;
        for (int o = 0; o < CQ; o++) s += l0[(size_t)k * CQ + o] * b1[o];
        b01[k] = s;
    }
}

// ---------------------------------------------------------------------------
// fp32 SGEMM-NT with S-stage cp.async pipeline (lin0 path).
// Out[b][m][n] = sum_k AT[k][m]*Bm[b][k][n] (+bias[m] if EPI==1)
// k strictly ascending. TAIL FIX: once issuing stops, wait_group 0 so the
// final tiles' cp.async groups are guaranteed complete before compute.
// ---------------------------------------------------------------------------
template<int M, int Kc, int Nn, int BM, int BN, int BK, int TM, int TN, int EPI, int S>
__global__ __launch_bounds__((BM/TM)*(BN/TN))
void gemm_nt_kernel(const float* __restrict__ AT,
                    const float* __restrict__ Bm,
                    const float* __restrict__ bias,
                    float* __restrict__ Out)
{
    constexpr int THREADS = (BM/TM)*(BN/TN);
    __shared__ float As[S][BK][BM];
    __shared__ float Bs[S][BK][BN];

    const int b   = blockIdx.z;
    const int bm0 = blockIdx.y * BM;
    const int bn0 = blockIdx.x * BN;
    const float* Bp = Bm + (size_t)b * Kc * Nn;
    float*       Op = Out + (size_t)b * M * Nn;

    const int tid = threadIdx.x;
    const int tx  = tid % (BN/TN);
    const int ty  = tid / (BN/TN);

    float acc[TM][TN];
    #pragma unroll
    for (int i = 0; i < TM; i++)
        #pragma unroll
        for (int j = 0; j < TN; j++) acc[i][j] = 0.f;

    auto load_tile = [&](int k0, int s) {
        #pragma unroll
        for (int i = tid; i < BK*BM/4; i += THREADS) {
            int k = (i*4) / BM, m = (i*4) % BM;
            cpa16(&As[s][k][m], &AT[(size_t)(k0 + k) * M + bm0 + m]);
        }
        #pragma unroll
        for (int i = tid; i < BK*BN/4; i += THREADS) {
            int k = (i*4) / BN, n = (i*4) % BN;
            cpa16(&Bs[s][k][n], &Bp[(size_t)(k0 + k) * Nn + bn0 + n]);
        }
        cpa_commit();
    };

    constexpr int NT = Kc / BK;
    #pragma unroll
    for (int p = 0; p < S - 1; p++) load_tile(p * BK, p);

    for (int t = 0; t < NT; t++) {
        // Tail-safe wait: while more groups will be issued after the one we
        // need, wait<S-2> suffices; in the drain phase force full wait.
        if (t < NT - (S - 1)) cpa_wait<S - 2>();
        else                  cpa_wait<0>();
        __syncthreads();
        if (t + S - 1 < NT) load_tile((t + S - 1) * BK, (t + S - 1) % S);

        const int s = t % S;
        float a[2][TM], bb[2][TN];
        #pragma unroll
        for (int v = 0; v < TM; v += 4)
            *reinterpret_cast<float4*>(&a[0][v]) =
                *reinterpret_cast<const float4*>(&As[s][0][ty*TM + v]);
        #pragma unroll
        for (int v = 0; v < TN; v += 4)
            *reinterpret_cast<float4*>(&bb[0][v]) =
                *reinterpret_cast<const float4*>(&Bs[s][0][tx*TN + v]);

        #pragma unroll
        for (int k = 0; k < BK; k++) {
            if (k + 1 < BK) {
                #pragma unroll
                for (int v = 0; v < TM; v += 4)
                    *reinterpret_cast<float4*>(&a[(k+1)&1][v]) =
                        *reinterpret_cast<const float4*>(&As[s][k+1][ty*TM + v]);
                #pragma unroll
                for (int v = 0; v < TN; v += 4)
                    *reinterpret_cast<float4*>(&bb[(k+1)&1][v]) =
                        *reinterpret_cast<const float4*>(&Bs[s][k+1][tx*TN + v]);
            }
            const int c = k & 1;
            #pragma unroll
            for (int i = 0; i < TM; i++)
                #pragma unroll
                for (int j = 0; j < TN; j++)
                    acc[i][j] += a[c][i] * bb[c][j];
        }
    }

    #pragma unroll
    for (int i = 0; i < TM; i++) {
        const int m = bm0 + ty * TM + i;
        float bval = 0.f;
        if (EPI == 1) bval = bias[m];
        #pragma unroll
        for (int j = 0; j < TN; j += 4) {
            const int n = bn0 + tx * TN + j;
            float vv[4];
            #pragma unroll
            for (int u = 0; u < 4; u++) vv[u] = acc[i][j + u];
            if (EPI == 1) {
                #pragma unroll
                for (int u = 0; u < 4; u++) vv[u] += bval;
            }
            float4 o; o.x = vv[0]; o.y = vv[1]; o.z = vv[2]; o.w = vv[3];
            *reinterpret_cast<float4*>(&Op[(size_t)m * Nn + n]) = o;
        }
    }
}

// ---------------------------------------------------------------------------
// Fused lin1 + rank + bf16 convert.
// Block: BM=32 channels x BN=512 tokens (one full rank row per channel).
// Each warp owns 4 complete rank rows; lane holds 16 of 512 values.
// GEMM k strictly ascending (bit-identical y2 vs unfused version).
// Threshold: exact 256th-largest via bitwise radix-select on the
// order-preserving uint32 mapping; compare in uint domain == fp32 compare.
// ---------------------------------------------------------------------------
__global__ __launch_bounds__(256) void lin1_rank_kernel(
    const float* __restrict__ l1T,    // [64][512] fp32 (k, c)
    const float* __restrict__ attn,   // [b][64][4096]
    __nv_bfloat16* __restrict__ y2h)  // [b][512][4096] bf16 out
{
    constexpr int BM = 32, BN = 512, BK = 8;
    constexpr int NT = KQ / BK;       // 8
    __shared__ float As[2][BK][BM];
    __shared__ float Bs[2][BK][BN];

    const int b   = blockIdx.z;
    const int bm0 = blockIdx.y * BM;
    const int bn0 = blockIdx.x * BN;
    const float* Bp = attn + (size_t)b * KQ * NQ;

    const int tid  = threadIdx.x;
    const int w    = tid / 32;   // warp -> 4 channels
    const int lane = tid % 32;

    float acc[4][16];
    #pragma unroll
    for (int i = 0; i < 4; i++)
        #pragma unroll
        for (int j = 0; j < 16; j++) acc[i][j] = 0.f;

    auto load_tile = [&](int k0, int s) {
        if (tid < 64) {
            int k = tid >> 3, m4 = (tid & 7) << 2;
            cpa16(&As[s][k][m4], &l1T[(size_t)(k0 + k) * CQ + bm0 + m4]);
        }
        #pragma unroll
        for (int r = 0; r < 4; r++) {
            int c = tid + r * 256;
            int k = c >> 7, p = (c & 127) << 2;
            cpa16(&Bs[s][k][p], &Bp[(size_t)(k0 + k) * NQ + bn0 + p]);
        }
        cpa_commit();
    };

    load_tile(0, 0);
    for (int t = 0; t < NT; t++) {
        cpa_wait<0>();
        __syncthreads();
        if (t + 1 < NT) load_tile((t + 1) * BK, (t + 1) & 1);
        const int s = t & 1;

        #pragma unroll
        for (int k = 0; k < BK; k++) {
            float4 av = *reinterpret_cast<const float4*>(&As[s][k][w * 4]);
            float a_[4] = {av.x, av.y, av.z, av.w};
            float bv[16];
            #pragma unroll
            for (int g = 0; g < 4; g++)
                *reinterpret_cast<float4*>(&bv[g * 4]) =
                    *reinterpret_cast<const float4*>(&Bs[s][k][g * 128 + lane * 4]);
            #pragma unroll
            for (int i = 0; i < 4; i++)
                #pragma unroll
                for (int j = 0; j < 16; j++)
                    acc[i][j] += a_[i] * bv[j];
        }
    }

    // Rank + scale + bf16 per channel row (warp-local, no sync needed)
    #pragma unroll
    for (int i = 0; i < 4; i++) {
        uint32_t u[16];
        #pragma unroll
        for (int j = 0; j < 16; j++) {
            uint32_t bits = __float_as_uint(acc[i][j]);
            u[j] = bits ^ (uint32_t)(((int)bits >> 31) | 0x80000000);
        }
        // exact 256th-largest via MSB-first radix select
        uint32_t prefix = 0;
        #pragma unroll
        for (int bit = 31; bit >= 0; bit--) {
            uint32_t cand = prefix | (1u << bit);
            int cnt = 0;
            #pragma unroll
            for (int j = 0; j < 16; j++) cnt += (u[j] >= cand);
            cnt = __reduce_add_sync(0xffffffffu, cnt);
            if (cnt >= 256) prefix = cand;
        }
        const uint32_t thr_u = prefix;

        const int m = bm0 + w * 4 + i;
        __nv_bfloat16* q = y2h + (size_t)b * CQ * NQ + (size_t)m * NQ + bn0;
        #pragma unroll
        for (int g = 0; g < 4; g++) {
            float v[4];
            #pragma unroll
            for (int uu = 0; uu < 4; uu++) {
                const int j = g * 4 + uu;
                v[uu] = (u[j] < thr_u) ? 0.75f * acc[i][j] : 1.25f * acc[i][j];
            }
            __nv_bfloat162 h0 = __float22bfloat162_rn(make_float2(v[0], v[1]));
            __nv_bfloat162 h1 = __float22bfloat162_rn(make_float2(v[2], v[3]));
            uint2 st;
            st.x = *reinterpret_cast<uint32_t*>(&h0);
            st.y = *reinterpret_cast<uint32_t*>(&h1);
            *reinterpret_cast<uint2*>(&q[g * 128 + lane * 4]) = st;
        }
    }
}

// ---------------------------------------------------------------------------
// BF16 tensor-core conv2 (post-rank). 3-stage cp.async pipeline (dyn smem).
// TAIL FIX applied (wait_group 0 in drain phase).
// Out[b][m][n] = relu( relu( sum_c W2[m][c]*y2[b][c][n] ) + x[b][m][n] )
// ---------------------------------------------------------------------------
__device__ __forceinline__ void mma_bf16(float d[4], const uint32_t a[4],
                                         const uint32_t b0, const uint32_t b1) {
    asm volatile(
        "mma.sync.aligned.m16n8k16.row.col.f32.bf16.bf16.f32 "
        "{%0,%1,%2,%3}, {%4,%5,%6,%7}, {%8,%9}, {%0,%1,%2,%3};"
        : "+f"(d[0]), "+f"(d[1]), "+f"(d[2]), "+f"(d[3])
        : "r"(a[0]), "r"(a[1]), "r"(a[2]), "r"(a[3]), "r"(b0), "r"(b1));
}
__device__ __forceinline__ void ldsm_x4_trans(uint32_t r[4], uint32_t addr) {
    asm volatile(
        "ldmatrix.sync.aligned.m8n8.x4.trans.shared.b16 {%0,%1,%2,%3}, [%4];"
        : "=r"(r[0]), "=r"(r[1]), "=r"(r[2]), "=r"(r[3]) : "r"(addr));
}

__global__ __launch_bounds__(256) void conv2_bf16_kernel(
    const __nv_bfloat16* __restrict__ w2h,  // [c][m] bf16
    const __nv_bfloat16* __restrict__ y2h,  // [b][c][n] bf16
    const float* __restrict__ x,            // residual fp32
    float* __restrict__ Out)
{
    constexpr int BM = 128, BN = 128, BK = 32, S = 3;
    extern __shared__ __align__(16) unsigned char cdyn[];
    typedef __nv_bfloat16 (*TileP)[BK][BM];
    TileP As = reinterpret_cast<TileP>(cdyn);
    TileP Bs = reinterpret_cast<TileP>(cdyn + (size_t)S * BK * BM * sizeof(__nv_bfloat16));

    const int b   = blockIdx.z;
    const int bm0 = blockIdx.y * BM;
    const int bn0 = blockIdx.x * BN;
    const __nv_bfloat16* Bp = y2h + (size_t)b * CQ * NQ;

    const int tid  = threadIdx.x;
    const int wid  = tid / 32;
    const int lane = tid % 32;
    const int wm   = wid % 2;
    const int wn   = wid / 2;
    const int m0w  = wm * 64;
    const int n0w  = wn * 32;
    const int g4   = lane / 4;
    const int t4   = lane % 4;

    float acc[4][4][4];
    #pragma unroll
    for (int i = 0; i < 4; i++)
        #pragma unroll
        for (int j = 0; j < 4; j++)
            #pragma unroll
            for (int u = 0; u < 4; u++) acc[i][j][u] = 0.f;

    auto swz = [](int e, int k) -> int {
        return ((((e >> 3) ^ (k & 7)) << 3) | (e & 7));
    };

    auto load_tile = [&](int k0, int s) {
        #pragma unroll
        for (int i = tid; i < 512; i += 256) {
            int k = i >> 4, cc = i & 15;
            cpa16(&As[s][k][(cc ^ (k & 7)) << 3],
                  &w2h[(size_t)(k0 + k) * CQ + bm0 + (cc << 3)]);
        }
        #pragma unroll
        for (int i = tid; i < 512; i += 256) {
            int k = i >> 4, cc = i & 15;
            cpa16(&Bs[s][k][(cc ^ (k & 7)) << 3],
                  &Bp[(size_t)(k0 + k) * NQ + bn0 + (cc << 3)]);
        }
        cpa_commit();
    };

    constexpr int NT = CQ / BK;            // 16
    load_tile(0, 0);
    load_tile(BK, 1);

    for (int t = 0; t < NT; t++) {
        if (t < NT - 2) cpa_wait<1>();
        else            cpa_wait<0>();      // drain phase: guarantee last tiles
        __syncthreads();
        if (t + 2 < NT) load_tile((t + 2) * BK, (t + 2) % S);
        const int s = t % S;

        #pragma unroll
        for (int ks = 0; ks < BK; ks += 16) {
            uint32_t a[4][4];
            const int l7  = lane & 7;
            const int kA  = ks + l7 + ((lane >> 4) << 3);
            const int mAo = (lane & 8);
            #pragma unroll
            for (int mt = 0; mt < 4; mt++) {
                const int mbase = m0w + mt * 16 + mAo;
                ldsm_x4_trans(a[mt], smem_u32(&As[s][kA][swz(mbase, kA)]));
            }
            uint32_t bfr[2][4];
            const int kB  = ks + l7 + (lane & 8);
            const int nBo = ((lane >> 4) << 3);
            #pragma unroll
            for (int np = 0; np < 2; np++) {
                const int nbase = n0w + np * 16 + nBo;
                ldsm_x4_trans(bfr[np], smem_u32(&Bs[s][kB][swz(nbase, kB)]));
            }
            #pragma unroll
            for (int mt = 0; mt < 4; mt++)
                #pragma unroll
                for (int nt = 0; nt < 4; nt++) {
                    const uint32_t* bp = bfr[nt >> 1];
                    if ((nt & 1) == 0) mma_bf16(acc[mt][nt], a[mt], bp[0], bp[1]);
                    else               mma_bf16(acc[mt][nt], a[mt], bp[2], bp[3]);
                }
        }
    }

    const float* Xp = x + (size_t)b * CQ * NQ;
    float*       Op = Out + (size_t)b * CQ * NQ;
    #pragma unroll
    for (int mt = 0; mt < 4; mt++) {
        #pragma unroll
        for (int nt = 0; nt < 4; nt++) {
            const int row0 = bm0 + m0w + mt * 16 + g4;
            const int col  = bn0 + n0w + nt * 8 + 2 * t4;
            #pragma unroll
            for (int half = 0; half < 2; half++) {
                const int row = row0 + half * 8;
                float2 r = *reinterpret_cast<const float2*>(&Xp[(size_t)row * NQ + col]);
                float v0 = fmaxf(fmaxf(acc[mt][nt][2*half + 0], 0.f) + r.x, 0.f);
                float v1 = fmaxf(fmaxf(acc[mt][nt][2*half + 1], 0.f) + r.y, 0.f);
                float2 o; o.x = v0; o.y = v1;
                *reinterpret_cast<float2*>(&Op[(size_t)row * NQ + col]) = o;
            }
        }
    }
}

// ---------------------------------------------------------------------------
// Softmax over token axis
// ---------------------------------------------------------------------------
__global__ __launch_bounds__(256) void softmax_kernel(float* __restrict__ attn)
{
    const int row = blockIdx.x;
    float* p = attn + (size_t)row * NQ;
    const int tid = threadIdx.x;
    __shared__ float red[256];

    float v[NQ / 256];
    float m = -INFINITY;
    #pragma unroll
    for (int i = 0; i < NQ / 256; i++) {
        v[i] = p[tid + i * 256];
        m = fmaxf(m, v[i]);
    }
    red[tid] = m; __syncthreads();
    for (int s = 128; s > 0; s >>= 1) {
        if (tid < s) red[tid] = fmaxf(red[tid], red[tid + s]);
        __syncthreads();
    }
    m = red[0]; __syncthreads();

    float s = 0.f;
    #pragma unroll
    for (int i = 0; i < NQ / 256; i++) {
        v[i] = expf(v[i] - m);
        s += v[i];
    }
    red[tid] = s; __syncthreads();
    for (int st = 128; st > 0; st >>= 1) {
        if (tid < st) red[tid] += red[tid + st];
        __syncthreads();
    }
    const float inv = 1.f / red[0];
    #pragma unroll
    for (int i = 0; i < NQ / 256; i++) p[tid + i * 256] = v[i] * inv;
}

// ---------------------------------------------------------------------------
// L1 renorm over latent axis K
// ---------------------------------------------------------------------------
__global__ __launch_bounds__(256) void renorm_kernel(float* __restrict__ attn)
{
    const int idx = blockIdx.x * blockDim.x + threadIdx.x;
    if (idx >= BQ * NQ) return;
    const int b = idx / NQ, n = idx % NQ;
    float* p = attn + (size_t)b * KQ * NQ + n;
    float s = 0.f;
    #pragma unroll
    for (int k = 0; k < KQ; k++) s += p[(size_t)k * NQ];
    const float inv = 1.f / (1e-9f + s);
    #pragma unroll
    for (int k = 0; k < KQ; k++) p[(size_t)k * NQ] *= inv;
}

// ---------------------------------------------------------------------------
// Launch
// ---------------------------------------------------------------------------
extern "C" void kernel_launch(void* const* d_in, const int* in_sizes, int n_in,
                              void* d_out, int out_size)
{
    const float* x  = (const float*)d_in[0];
    const float* w1 = (const float*)d_in[1];
    const float* b1 = (const float*)d_in[2];
    const float* l0 = (const float*)d_in[3];
    const float* l1 = (const float*)d_in[4];
    const float* w2 = (const float*)d_in[5];
    float* out = (float*)d_out;

    void *ap_, *y2h_, *w2h_, *l1t_, *w01_, *b01_;
    cudaGetSymbolAddress(&ap_, g_attn);
    cudaGetSymbolAddress(&y2h_, g_y2h);
    cudaGetSymbolAddress(&w2h_, g_w2h);
    cudaGetSymbolAddress(&l1t_, g_l1T);
    cudaGetSymbolAddress(&w01_, g_w01T);
    cudaGetSymbolAddress(&b01_, g_b01);
    float*         attn = (float*)ap_;
    __nv_bfloat16* y2h  = (__nv_bfloat16*)y2h_;
    __nv_bfloat16* w2h  = (__nv_bfloat16*)w2h_;
    float*         l1T  = (float*)l1t_;
    float*         w01T = (float*)w01_;
    float*         b01  = (float*)b01_;

    // conv2 needs 48KB dynamic smem (3-stage pipeline)
    const int conv2_smem = 3 * 32 * 128 * 2 * 2;   // S*BK*(BM+BN)*sizeof(bf16)
    cudaFuncSetAttribute(conv2_bf16_kernel,
                         cudaFuncAttributeMaxDynamicSharedMemorySize, conv2_smem);

    // Weight prep
    transpose_bf16_kernel<<<dim3(CQ/32, CQ/32), dim3(32, 8)>>>(w2, w2h, CQ, CQ);
    transpose_kernel<<<dim3(KQ/32, CQ/32), dim3(32, 8)>>>(l1, l1T, CQ, KQ);
    fuse_w01_kernel<<<dim3(CQ/16, KQ/16), dim3(16, 16)>>>(w1, l0, b1, w01T, b01);

    // Fused conv1+lin0 (fp32): attn = (L0@W1) @ x + (L0@b1)
    gemm_nt_kernel<KQ, CQ, NQ, 64, 64, 16, 4, 8, 1, 3>
        <<<dim3(NQ / 64, 1, BQ), 128>>>(w01T, x, b01, attn);

    softmax_kernel<<<BQ * KQ, 256>>>(attn);
    renorm_kernel<<<(BQ * NQ) / 256, 256>>>(attn);

    // Fused lin1 + rank + bf16 convert
    lin1_rank_kernel<<<dim3(NQ / 512, CQ / 32, BQ), 256>>>(l1T, attn, y2h);

    // conv2 via bf16 tensor cores + fused relu/residual/relu
    conv2_bf16_kernel<<<dim3(NQ / 128, CQ / 128, BQ), 256, conv2_smem>>>(
        w2h, y2h, x, out);
}

// round 9
// speedup vs baseline: 5.5410x; 1.0680x over previous
#include <cuda_runtime.h>
#include <cuda_bf16.h>
#include <math.h>
#include <stdint.h>

// Problem dims
#define BQ 16
#define CQ 512
#define NQ 4096   // H*W
#define KQ 64

// Scratch (allocation-free rule: device globals)
__device__ __align__(128) float         g_attn[BQ * KQ * NQ]; // attn logits/probs (softmaxed)
__device__ __align__(128) float         g_rs  [BQ * NQ];      // 1/(1e-9+colsum)
__device__ __align__(128) __nv_bfloat16 g_y2h [BQ * CQ * NQ]; // ranked y2, bf16 [b][c][n]
__device__ __align__(128) __nv_bfloat16 g_w2h [CQ * CQ];      // conv2 weight [c][o] bf16
__device__ __align__(128) float         g_l1T [KQ * CQ];      // lin1 weight [k][c] fp32
__device__ __align__(128) float         g_w01T[CQ * KQ];      // fused (L0@W1)^T [c][k]
__device__ __align__(128) float         g_b01 [KQ];           // fused bias L0@b1

// ---------------------------------------------------------------------------
// helpers
// ---------------------------------------------------------------------------
__device__ __forceinline__ void cpa16(void* smem_dst, const void* gmem_src) {
    unsigned sa = (unsigned)__cvta_generic_to_shared(smem_dst);
    asm volatile("cp.async.ca.shared.global [%0], [%1], 16;" :: "r"(sa), "l"(gmem_src));
}
__device__ __forceinline__ void cpa_commit() {
    asm volatile("cp.async.commit_group;" ::: "memory");
}
template<int N>
__device__ __forceinline__ void cpa_wait() {
    asm volatile("cp.async.wait_group %0;" :: "n"(N) : "memory");
}
__device__ __forceinline__ uint32_t smem_u32(const void* p) {
    return (uint32_t)__cvta_generic_to_shared(p);
}

// ---------------------------------------------------------------------------
// Transpose fp32: AT[k][m] = A[m][k]
// ---------------------------------------------------------------------------
__global__ __launch_bounds__(256) void transpose_kernel(
    const float* __restrict__ A, float* __restrict__ AT, int M, int K)
{
    __shared__ float t[32][33];
    const int m0 = blockIdx.y * 32, k0 = blockIdx.x * 32;
    const int x = threadIdx.x, y = threadIdx.y;
    #pragma unroll
    for (int yy = y; yy < 32; yy += 8)
        t[yy][x] = A[(size_t)(m0 + yy) * K + k0 + x];
    __syncthreads();
    #pragma unroll
    for (int yy = y; yy < 32; yy += 8)
        AT[(size_t)(k0 + yy) * M + m0 + x] = t[x][yy];
}

// Transpose + bf16 convert: AT[k][m] = bf16(A[m][k])
__global__ __launch_bounds__(256) void transpose_bf16_kernel(
    const float* __restrict__ A, __nv_bfloat16* __restrict__ AT, int M, int K)
{
    __shared__ float t[32][33];
    const int m0 = blockIdx.y * 32, k0 = blockIdx.x * 32;
    const int x = threadIdx.x, y = threadIdx.y;
    #pragma unroll
    for (int yy = y; yy < 32; yy += 8)
        t[yy][x] = A[(size_t)(m0 + yy) * K + k0 + x];
    __syncthreads();
    #pragma unroll
    for (int yy = y; yy < 32; yy += 8)
        AT[(size_t)(k0 + yy) * M + m0 + x] = __float2bfloat16_rn(t[x][yy]);
}

// ---------------------------------------------------------------------------
// Weight fusion: W01T[c][k] = sum_o W1[o][c] * L0[k][o], b01[k] = L0@b1
// ---------------------------------------------------------------------------
__global__ __launch_bounds__(256) void fuse_w01_kernel(
    const float* __restrict__ w1, const float* __restrict__ l0,
    const float* __restrict__ b1, float* __restrict__ w01T, float* __restrict__ b01)
{
    __shared__ float sw[16][17];
    __shared__ float sl[16][17];
    const int c0 = blockIdx.x * 16, k0 = blockIdx.y * 16;
    const int tx = threadIdx.x, ty = threadIdx.y;
    float acc = 0.f;
    for (int o0 = 0; o0 < CQ; o0 += 16) {
        sw[ty][tx] = w1[(size_t)(o0 + ty) * CQ + c0 + tx];
        sl[ty][tx] = l0[(size_t)(k0 + ty) * CQ + o0 + tx];
        __syncthreads();
        #pragma unroll
        for (int o = 0; o < 16; o++)
            acc += sw[o][tx] * sl[ty][o];
        __syncthreads();
    }
    w01T[(size_t)(c0 + tx) * KQ + k0 + ty] = acc;
    if (blockIdx.x == 0 && tx == 0) {
        const int k = k0 + ty;
        float s = 0.f;
        for (int o = 0; o < CQ; o++) s += l0[(size_t)k * CQ + o] * b1[o];
        b01[k] = s;
    }
}

// ---------------------------------------------------------------------------
// fp32 SGEMM-NT with S-stage cp.async pipeline (lin0 path). Tail-safe waits.
// ---------------------------------------------------------------------------
template<int M, int Kc, int Nn, int BM, int BN, int BK, int TM, int TN, int EPI, int S>
__global__ __launch_bounds__((BM/TM)*(BN/TN))
void gemm_nt_kernel(const float* __restrict__ AT,
                    const float* __restrict__ Bm,
                    const float* __restrict__ bias,
                    float* __restrict__ Out)
{
    constexpr int THREADS = (BM/TM)*(BN/TN);
    __shared__ float As[S][BK][BM];
    __shared__ float Bs[S][BK][BN];

    const int b   = blockIdx.z;
    const int bm0 = blockIdx.y * BM;
    const int bn0 = blockIdx.x * BN;
    const float* Bp = Bm + (size_t)b * Kc * Nn;
    float*       Op = Out + (size_t)b * M * Nn;

    const int tid = threadIdx.x;
    const int tx  = tid % (BN/TN);
    const int ty  = tid / (BN/TN);

    float acc[TM][TN];
    #pragma unroll
    for (int i = 0; i < TM; i++)
        #pragma unroll
        for (int j = 0; j < TN; j++) acc[i][j] = 0.f;

    auto load_tile = [&](int k0, int s) {
        #pragma unroll
        for (int i = tid; i < BK*BM/4; i += THREADS) {
            int k = (i*4) / BM, m = (i*4) % BM;
            cpa16(&As[s][k][m], &AT[(size_t)(k0 + k) * M + bm0 + m]);
        }
        #pragma unroll
        for (int i = tid; i < BK*BN/4; i += THREADS) {
            int k = (i*4) / BN, n = (i*4) % BN;
            cpa16(&Bs[s][k][n], &Bp[(size_t)(k0 + k) * Nn + bn0 + n]);
        }
        cpa_commit();
    };

    constexpr int NT = Kc / BK;
    #pragma unroll
    for (int p = 0; p < S - 1; p++) load_tile(p * BK, p);

    for (int t = 0; t < NT; t++) {
        if (t < NT - (S - 1)) cpa_wait<S - 2>();
        else                  cpa_wait<0>();
        __syncthreads();
        if (t + S - 1 < NT) load_tile((t + S - 1) * BK, (t + S - 1) % S);

        const int s = t % S;
        float a[2][TM], bb[2][TN];
        #pragma unroll
        for (int v = 0; v < TM; v += 4)
            *reinterpret_cast<float4*>(&a[0][v]) =
                *reinterpret_cast<const float4*>(&As[s][0][ty*TM + v]);
        #pragma unroll
        for (int v = 0; v < TN; v += 4)
            *reinterpret_cast<float4*>(&bb[0][v]) =
                *reinterpret_cast<const float4*>(&Bs[s][0][tx*TN + v]);

        #pragma unroll
        for (int k = 0; k < BK; k++) {
            if (k + 1 < BK) {
                #pragma unroll
                for (int v = 0; v < TM; v += 4)
                    *reinterpret_cast<float4*>(&a[(k+1)&1][v]) =
                        *reinterpret_cast<const float4*>(&As[s][k+1][ty*TM + v]);
                #pragma unroll
                for (int v = 0; v < TN; v += 4)
                    *reinterpret_cast<float4*>(&bb[(k+1)&1][v]) =
                        *reinterpret_cast<const float4*>(&Bs[s][k+1][tx*TN + v]);
            }
            const int c = k & 1;
            #pragma unroll
            for (int i = 0; i < TM; i++)
                #pragma unroll
                for (int j = 0; j < TN; j++)
                    acc[i][j] += a[c][i] * bb[c][j];
        }
    }

    #pragma unroll
    for (int i = 0; i < TM; i++) {
        const int m = bm0 + ty * TM + i;
        float bval = 0.f;
        if (EPI == 1) bval = bias[m];
        #pragma unroll
        for (int j = 0; j < TN; j += 4) {
            const int n = bn0 + tx * TN + j;
            float vv[4];
            #pragma unroll
            for (int u = 0; u < 4; u++) vv[u] = acc[i][j + u];
            if (EPI == 1) {
                #pragma unroll
                for (int u = 0; u < 4; u++) vv[u] += bval;
            }
            float4 o; o.x = vv[0]; o.y = vv[1]; o.z = vv[2]; o.w = vv[3];
            *reinterpret_cast<float4*>(&Op[(size_t)m * Nn + n]) = o;
        }
    }
}

// ---------------------------------------------------------------------------
// Softmax over token axis
// ---------------------------------------------------------------------------
__global__ __launch_bounds__(256) void softmax_kernel(float* __restrict__ attn)
{
    const int row = blockIdx.x;
    float* p = attn + (size_t)row * NQ;
    const int tid = threadIdx.x;
    __shared__ float red[256];

    float v[NQ / 256];
    float m = -INFINITY;
    #pragma unroll
    for (int i = 0; i < NQ / 256; i++) {
        v[i] = p[tid + i * 256];
        m = fmaxf(m, v[i]);
    }
    red[tid] = m; __syncthreads();
    for (int s = 128; s > 0; s >>= 1) {
        if (tid < s) red[tid] = fmaxf(red[tid], red[tid + s]);
        __syncthreads();
    }
    m = red[0]; __syncthreads();

    float s = 0.f;
    #pragma unroll
    for (int i = 0; i < NQ / 256; i++) {
        v[i] = expf(v[i] - m);
        s += v[i];
    }
    red[tid] = s; __syncthreads();
    for (int st = 128; st > 0; st >>= 1) {
        if (tid < st) red[tid] += red[tid + st];
        __syncthreads();
    }
    const float inv = 1.f / red[0];
    #pragma unroll
    for (int i = 0; i < NQ / 256; i++) p[tid + i * 256] = v[i] * inv;
}

// ---------------------------------------------------------------------------
// Column-sum reciprocal over latent axis: rs[b][n] = 1/(1e-9 + sum_k attn)
// (the divide itself is folded into lin1_rank)
// ---------------------------------------------------------------------------
__global__ __launch_bounds__(256) void colsum_kernel(
    const float* __restrict__ attn, float* __restrict__ rs)
{
    const int idx = blockIdx.x * blockDim.x + threadIdx.x;
    if (idx >= BQ * NQ) return;
    const int b = idx / NQ, n = idx % NQ;
    const float* p = attn + (size_t)b * KQ * NQ + n;
    float s = 0.f;
    #pragma unroll
    for (int k = 0; k < KQ; k++) s += p[(size_t)k * NQ];
    rs[idx] = 1.f / (1e-9f + s);
}

// ---------------------------------------------------------------------------
// Fused lin1 + renorm-scale + rank + bf16 convert.
// Block: 32 channels x 512 tokens. Warp owns 4 complete rank rows.
// Threshold: exact 256th-largest via bitwise radix-select (warp reduce).
// ---------------------------------------------------------------------------
__global__ __launch_bounds__(256) void lin1_rank_kernel(
    const float* __restrict__ l1T,    // [64][512] fp32 (k, c)
    const float* __restrict__ attn,   // [b][64][4096] (softmaxed, NOT renormed)
    const float* __restrict__ rs,     // [b][4096] reciprocal colsums
    __nv_bfloat16* __restrict__ y2h)  // [b][512][4096] bf16 out
{
    constexpr int BM = 32, BN = 512, BK = 8;
    constexpr int NT = KQ / BK;       // 8
    __shared__ float As[2][BK][BM];
    __shared__ float Bs[2][BK][BN];

    const int b   = blockIdx.z;
    const int bm0 = blockIdx.y * BM;
    const int bn0 = blockIdx.x * BN;
    const float* Bp = attn + (size_t)b * KQ * NQ;

    const int tid  = threadIdx.x;
    const int w    = tid / 32;   // warp -> 4 channels
    const int lane = tid % 32;

    float acc[4][16];
    #pragma unroll
    for (int i = 0; i < 4; i++)
        #pragma unroll
        for (int j = 0; j < 16; j++) acc[i][j] = 0.f;

    auto load_tile = [&](int k0, int s) {
        if (tid < 64) {
            int k = tid >> 3, m4 = (tid & 7) << 2;
            cpa16(&As[s][k][m4], &l1T[(size_t)(k0 + k) * CQ + bm0 + m4]);
        }
        #pragma unroll
        for (int r = 0; r < 4; r++) {
            int c = tid + r * 256;
            int k = c >> 7, p = (c & 127) << 2;
            cpa16(&Bs[s][k][p], &Bp[(size_t)(k0 + k) * NQ + bn0 + p]);
        }
        cpa_commit();
    };

    load_tile(0, 0);
    for (int t = 0; t < NT; t++) {
        cpa_wait<0>();
        __syncthreads();
        if (t + 1 < NT) load_tile((t + 1) * BK, (t + 1) & 1);
        const int s = t & 1;

        #pragma unroll
        for (int k = 0; k < BK; k++) {
            float4 av = *reinterpret_cast<const float4*>(&As[s][k][w * 4]);
            float a_[4] = {av.x, av.y, av.z, av.w};
            float bv[16];
            #pragma unroll
            for (int g = 0; g < 4; g++)
                *reinterpret_cast<float4*>(&bv[g * 4]) =
                    *reinterpret_cast<const float4*>(&Bs[s][k][g * 128 + lane * 4]);
            #pragma unroll
            for (int i = 0; i < 4; i++)
                #pragma unroll
                for (int j = 0; j < 16; j++)
                    acc[i][j] += a_[i] * bv[j];
        }
    }

    // renorm scale: acc[i][j] *= rs[b][n]
    {
        const float* rp = rs + (size_t)b * NQ + bn0;
        #pragma unroll
        for (int g = 0; g < 4; g++) {
            float4 rv = *reinterpret_cast<const float4*>(&rp[g * 128 + lane * 4]);
            float rr[4] = {rv.x, rv.y, rv.z, rv.w};
            #pragma unroll
            for (int i = 0; i < 4; i++)
                #pragma unroll
                for (int uu = 0; uu < 4; uu++)
                    acc[i][g * 4 + uu] *= rr[uu];
        }
    }

    // Rank + scale + bf16 per channel row (warp-local, no sync needed)
    #pragma unroll
    for (int i = 0; i < 4; i++) {
        uint32_t u[16];
        #pragma unroll
        for (int j = 0; j < 16; j++) {
            uint32_t bits = __float_as_uint(acc[i][j]);
            u[j] = bits ^ (uint32_t)(((int)bits >> 31) | 0x80000000);
        }
        uint32_t prefix = 0;
        #pragma unroll
        for (int bit = 31; bit >= 0; bit--) {
            uint32_t cand = prefix | (1u << bit);
            int cnt = 0;
            #pragma unroll
            for (int j = 0; j < 16; j++) cnt += (u[j] >= cand);
            cnt = __reduce_add_sync(0xffffffffu, cnt);
            if (cnt >= 256) prefix = cand;
        }
        const uint32_t thr_u = prefix;

        const int m = bm0 + w * 4 + i;
        __nv_bfloat16* q = y2h + (size_t)b * CQ * NQ + (size_t)m * NQ + bn0;
        #pragma unroll
        for (int g = 0; g < 4; g++) {
            float v[4];
            #pragma unroll
            for (int uu = 0; uu < 4; uu++) {
                const int j = g * 4 + uu;
                v[uu] = (u[j] < thr_u) ? 0.75f * acc[i][j] : 1.25f * acc[i][j];
            }
            __nv_bfloat162 h0 = __float22bfloat162_rn(make_float2(v[0], v[1]));
            __nv_bfloat162 h1 = __float22bfloat162_rn(make_float2(v[2], v[3]));
            uint2 st;
            st.x = *reinterpret_cast<uint32_t*>(&h0);
            st.y = *reinterpret_cast<uint32_t*>(&h1);
            *reinterpret_cast<uint2*>(&q[g * 128 + lane * 4]) = st;
        }
    }
}

// ---------------------------------------------------------------------------
// BF16 tensor-core conv2 (mma.sync — tcgen05 unavailable: harness lowers to
// .target sm_103 which rejects tcgen05). 3-stage cp.async pipeline (dyn smem).
// Out[b][m][n] = relu( relu( sum_c W2[m][c]*y2[b][c][n] ) + x[b][m][n] )
// ---------------------------------------------------------------------------
__device__ __forceinline__ void mma_bf16(float d[4], const uint32_t a[4],
                                         const uint32_t b0, const uint32_t b1) {
    asm volatile(
        "mma.sync.aligned.m16n8k16.row.col.f32.bf16.bf16.f32 "
        "{%0,%1,%2,%3}, {%4,%5,%6,%7}, {%8,%9}, {%0,%1,%2,%3};"
        : "+f"(d[0]), "+f"(d[1]), "+f"(d[2]), "+f"(d[3])
        : "r"(a[0]), "r"(a[1]), "r"(a[2]), "r"(a[3]), "r"(b0), "r"(b1));
}
__device__ __forceinline__ void ldsm_x4_trans(uint32_t r[4], uint32_t addr) {
    asm volatile(
        "ldmatrix.sync.aligned.m8n8.x4.trans.shared.b16 {%0,%1,%2,%3}, [%4];"
        : "=r"(r[0]), "=r"(r[1]), "=r"(r[2]), "=r"(r[3]) : "r"(addr));
}

__global__ __launch_bounds__(256) void conv2_bf16_kernel(
    const __nv_bfloat16* __restrict__ w2h,  // [c][m] bf16
    const __nv_bfloat16* __restrict__ y2h,  // [b][c][n] bf16
    const float* __restrict__ x,            // residual fp32
    float* __restrict__ Out)
{
    constexpr int BM = 128, BN = 128, BK = 32, S = 3;
    extern __shared__ __align__(16) unsigned char cdyn[];
    typedef __nv_bfloat16 (*TileP)[BK][BM];
    TileP As = reinterpret_cast<TileP>(cdyn);
    TileP Bs = reinterpret_cast<TileP>(cdyn + (size_t)S * BK * BM * sizeof(__nv_bfloat16));

    const int b   = blockIdx.z;
    const int bm0 = blockIdx.y * BM;
    const int bn0 = blockIdx.x * BN;
    const __nv_bfloat16* Bp = y2h + (size_t)b * CQ * NQ;

    const int tid  = threadIdx.x;
    const int wid  = tid / 32;
    const int lane = tid % 32;
    const int wm   = wid % 2;
    const int wn   = wid / 2;
    const int m0w  = wm * 64;
    const int n0w  = wn * 32;
    const int g4   = lane / 4;
    const int t4   = lane % 4;

    float acc[4][4][4];
    #pragma unroll
    for (int i = 0; i < 4; i++)
        #pragma unroll
        for (int j = 0; j < 4; j++)
            #pragma unroll
            for (int u = 0; u < 4; u++) acc[i][j][u] = 0.f;

    auto swz = [](int e, int k) -> int {
        return ((((e >> 3) ^ (k & 7)) << 3) | (e & 7));
    };

    auto load_tile = [&](int k0, int s) {
        #pragma unroll
        for (int i = tid; i < 512; i += 256) {
            int k = i >> 4, cc = i & 15;
            cpa16(&As[s][k][(cc ^ (k & 7)) << 3],
                  &w2h[(size_t)(k0 + k) * CQ + bm0 + (cc << 3)]);
        }
        #pragma unroll
        for (int i = tid; i < 512; i += 256) {
            int k = i >> 4, cc = i & 15;
            cpa16(&Bs[s][k][(cc ^ (k & 7)) << 3],
                  &Bp[(size_t)(k0 + k) * NQ + bn0 + (cc << 3)]);
        }
        cpa_commit();
    };

    constexpr int NT = CQ / BK;            // 16
    load_tile(0, 0);
    load_tile(BK, 1);

    for (int t = 0; t < NT; t++) {
        if (t < NT - 2) cpa_wait<1>();
        else            cpa_wait<0>();      // drain phase: guarantee last tiles
        __syncthreads();
        if (t + 2 < NT) load_tile((t + 2) * BK, (t + 2) % S);
        const int s = t % S;

        #pragma unroll
        for (int ks = 0; ks < BK; ks += 16) {
            uint32_t a[4][4];
            const int l7  = lane & 7;
            const int kA  = ks + l7 + ((lane >> 4) << 3);
            const int mAo = (lane & 8);
            #pragma unroll
            for (int mt = 0; mt < 4; mt++) {
                const int mbase = m0w + mt * 16 + mAo;
                ldsm_x4_trans(a[mt], smem_u32(&As[s][kA][swz(mbase, kA)]));
            }
            uint32_t bfr[2][4];
            const int kB  = ks + l7 + (lane & 8);
            const int nBo = ((lane >> 4) << 3);
            #pragma unroll
            for (int np = 0; np < 2; np++) {
                const int nbase = n0w + np * 16 + nBo;
                ldsm_x4_trans(bfr[np], smem_u32(&Bs[s][kB][swz(nbase, kB)]));
            }
            #pragma unroll
            for (int mt = 0; mt < 4; mt++)
                #pragma unroll
                for (int nt = 0; nt < 4; nt++) {
                    const uint32_t* bp = bfr[nt >> 1];
                    if ((nt & 1) == 0) mma_bf16(acc[mt][nt], a[mt], bp[0], bp[1]);
                    else               mma_bf16(acc[mt][nt], a[mt], bp[2], bp[3]);
                }
        }
    }

    const float* Xp = x + (size_t)b * CQ * NQ;
    float*       Op = Out + (size_t)b * CQ * NQ;
    #pragma unroll
    for (int mt = 0; mt < 4; mt++) {
        #pragma unroll
        for (int nt = 0; nt < 4; nt++) {
            const int row0 = bm0 + m0w + mt * 16 + g4;
            const int col  = bn0 + n0w + nt * 8 + 2 * t4;
            #pragma unroll
            for (int half = 0; half < 2; half++) {
                const int row = row0 + half * 8;
                float2 r = *reinterpret_cast<const float2*>(&Xp[(size_t)row * NQ + col]);
                float v0 = fmaxf(fmaxf(acc[mt][nt][2*half + 0], 0.f) + r.x, 0.f);
                float v1 = fmaxf(fmaxf(acc[mt][nt][2*half + 1], 0.f) + r.y, 0.f);
                float2 o; o.x = v0; o.y = v1;
                *reinterpret_cast<float2*>(&Op[(size_t)row * NQ + col]) = o;
            }
        }
    }
}

// ---------------------------------------------------------------------------
// Launch
// ---------------------------------------------------------------------------
extern "C" void kernel_launch(void* const* d_in, const int* in_sizes, int n_in,
                              void* d_out, int out_size)
{
    const float* x  = (const float*)d_in[0];
    const float* w1 = (const float*)d_in[1];
    const float* b1 = (const float*)d_in[2];
    const float* l0 = (const float*)d_in[3];
    const float* l1 = (const float*)d_in[4];
    const float* w2 = (const float*)d_in[5];
    float* out = (float*)d_out;

    void *ap_, *rs_, *y2h_, *w2h_, *l1t_, *w01_, *b01_;
    cudaGetSymbolAddress(&ap_, g_attn);
    cudaGetSymbolAddress(&rs_, g_rs);
    cudaGetSymbolAddress(&y2h_, g_y2h);
    cudaGetSymbolAddress(&w2h_, g_w2h);
    cudaGetSymbolAddress(&l1t_, g_l1T);
    cudaGetSymbolAddress(&w01_, g_w01T);
    cudaGetSymbolAddress(&b01_, g_b01);
    float*         attn = (float*)ap_;
    float*         rs   = (float*)rs_;
    __nv_bfloat16* y2h  = (__nv_bfloat16*)y2h_;
    __nv_bfloat16* w2h  = (__nv_bfloat16*)w2h_;
    float*         l1T  = (float*)l1t_;
    float*         w01T = (float*)w01_;
    float*         b01  = (float*)b01_;

    // conv2 needs 48KB dynamic smem (3-stage pipeline)
    const int conv2_smem = 3 * 32 * 128 * 2 * 2;
    cudaFuncSetAttribute(conv2_bf16_kernel,
                         cudaFuncAttributeMaxDynamicSharedMemorySize, conv2_smem);

    // Weight prep
    transpose_bf16_kernel<<<dim3(CQ/32, CQ/32), dim3(32, 8)>>>(w2, w2h, CQ, CQ);
    transpose_kernel<<<dim3(KQ/32, CQ/32), dim3(32, 8)>>>(l1, l1T, CQ, KQ);
    fuse_w01_kernel<<<dim3(CQ/16, KQ/16), dim3(16, 16)>>>(w1, l0, b1, w01T, b01);

    // Fused conv1+lin0 (fp32): attn = (L0@W1) @ x + (L0@b1)
    // Retiled TM=8 x TN=8 (halves LDS per FMA vs R7's 4x8)
    gemm_nt_kernel<KQ, CQ, NQ, 64, 128, 16, 8, 8, 1, 3>
        <<<dim3(NQ / 128, 1, BQ), 128>>>(w01T, x, b01, attn);

    softmax_kernel<<<BQ * KQ, 256>>>(attn);
    colsum_kernel<<<(BQ * NQ) / 256, 256>>>(attn, rs);

    // Fused lin1 + renorm + rank + bf16
    lin1_rank_kernel<<<dim3(NQ / 512, CQ / 32, BQ), 256>>>(l1T, attn, rs, y2h);

    // conv2 via bf16 mma.sync + fused relu/residual/relu
    conv2_bf16_kernel<<<dim3(NQ / 128, CQ / 128, BQ), 256, conv2_smem>>>(
        w2h, y2h, x, out);
}